// round 1
// baseline (speedup 1.0000x reference)
#include <cuda_runtime.h>

// Problem constants
#define B_    2
#define C_    128
#define T_    4
#define S_    16384      // T*H*W
#define NH_   32
#define N_    1024       // T*h*w = 4*16*16
#define TABSZ 6727       // (2T-1)*(2h-1)*(2w-1) = 7*31*31
#define EPS_  1e-5f

// ---------------- scratch (static device globals; no runtime alloc) -------
__device__ float g_z[3][B_][C_][S_];        // q,k,v projections (50.3 MB)
__device__ float g_mean[3][B_][32];
__device__ float g_rstd[3][B_][32];
__device__ float g_qp[B_][NH_][N_][4];      // pooled, normalized Q
__device__ float g_kp[B_][NH_][N_][4];      // pooled, normalized K
__device__ float g_vp[B_][NH_][N_][64];     // normalized V, [m][d*16+p]

// ---------------- f32x2 helpers (B300 2x fp32 path) -----------------------
__device__ __forceinline__ unsigned long long packf2(float v) {
    unsigned long long r; unsigned int u = __float_as_uint(v);
    asm("mov.b64 %0, {%1, %1};" : "=l"(r) : "r"(u));
    return r;
}
__device__ __forceinline__ void ffma2(unsigned long long& d,
                                      unsigned long long a, unsigned long long b) {
    asm("fma.rn.f32x2 %0, %1, %2, %0;" : "+l"(d) : "l"(a), "l"(b));
}
__device__ __forceinline__ void fmul2(unsigned long long& d, unsigned long long a) {
    asm("mul.rn.f32x2 %0, %0, %1;" : "+l"(d) : "l"(a));
}

// ================= K1: 1x1x1 projections (SGEMM 128 x 16384 x 128) =========
// grid (S_/128, B_, 3), block 256, dynamic smem = (128*129 + 128*128)*4 B
#define PROJ_SMEM_BYTES ((128*129 + 128*128) * 4)

__global__ __launch_bounds__(256) void proj_kernel(
    const float* __restrict__ x, const float* __restrict__ Wq,
    const float* __restrict__ Wk, const float* __restrict__ Wv) {
    extern __shared__ float sm[];
    float* Wt = sm;                 // [c][o], row pitch 129 (conflict-free)
    float* Xs = sm + 128 * 129;     // [c][sj], row pitch 128

    const int pr = blockIdx.z;
    const float* Wsel = (pr == 0) ? Wq : ((pr == 1) ? Wk : Wv);
    const int b  = blockIdx.y;
    const int s0 = blockIdx.x << 7;
    const int tid = threadIdx.x;
    const float* xb = x + (size_t)b * C_ * S_;

    for (int i = tid; i < 16384; i += 256) {          // W transpose load
        int o = i >> 7, c = i & 127;
        Wt[c * 129 + o] = Wsel[i];
    }
    for (int i = tid; i < 16384; i += 256) {          // X tile load (coalesced)
        int c = i >> 7, sj = i & 127;
        Xs[(c << 7) + sj] = xb[c * S_ + s0 + sj];
    }
    __syncthreads();

    const int ty = tid >> 4, tx = tid & 15;
    const int ob = ty << 3, sb = tx << 3;
    float acc[8][8];
#pragma unroll
    for (int i = 0; i < 8; i++)
#pragma unroll
        for (int j = 0; j < 8; j++) acc[i][j] = 0.f;

#pragma unroll 4
    for (int c = 0; c < 128; c++) {
        float a[8];
#pragma unroll
        for (int i = 0; i < 8; i++) a[i] = Wt[c * 129 + ob + i];
        float4 b0 = *(const float4*)&Xs[(c << 7) + sb];
        float4 b1 = *(const float4*)&Xs[(c << 7) + sb + 4];
        float bf[8] = {b0.x, b0.y, b0.z, b0.w, b1.x, b1.y, b1.z, b1.w};
#pragma unroll
        for (int i = 0; i < 8; i++)
#pragma unroll
            for (int j = 0; j < 8; j++) acc[i][j] = fmaf(a[i], bf[j], acc[i][j]);
    }
#pragma unroll
    for (int i = 0; i < 8; i++) {
        float* dst = &g_z[pr][b][ob + i][s0 + sb];
        *(float4*)dst       = make_float4(acc[i][0], acc[i][1], acc[i][2], acc[i][3]);
        *(float4*)(dst + 4) = make_float4(acc[i][4], acc[i][5], acc[i][6], acc[i][7]);
    }
}

// ================= K2: GroupNorm stats (E[x^2] - mu^2) =====================
// grid (32, B_, 3), block 256
__global__ __launch_bounds__(256) void stats_kernel() {
    const int grp = blockIdx.x, b = blockIdx.y, pr = blockIdx.z;
    const float* base = &g_z[pr][b][grp << 2][0];   // 4 channels contiguous
    float s = 0.f, s2 = 0.f;
    for (int i = threadIdx.x; i < 4 * S_; i += 256) {
        float v = base[i]; s += v; s2 = fmaf(v, v, s2);
    }
#pragma unroll
    for (int o = 16; o; o >>= 1) {
        s  += __shfl_xor_sync(0xffffffffu, s, o);
        s2 += __shfl_xor_sync(0xffffffffu, s2, o);
    }
    __shared__ float rs[8], rs2[8];
    int w = threadIdx.x >> 5;
    if ((threadIdx.x & 31) == 0) { rs[w] = s; rs2[w] = s2; }
    __syncthreads();
    if (threadIdx.x == 0) {
        float ts = 0.f, ts2 = 0.f;
#pragma unroll
        for (int i = 0; i < 8; i++) { ts += rs[i]; ts2 += rs2[i]; }
        float mean = ts / (4.f * S_);
        float var  = ts2 / (4.f * S_) - mean * mean;
        g_mean[pr][b][grp] = mean;
        g_rstd[pr][b][grp] = rsqrtf(var + EPS_);
    }
}

// ================= K3: normalize + pool + patch permute ====================
// one thread per (b, c, n); grid 1024 x 256
__global__ __launch_bounds__(256) void prep_kernel(
    const float* __restrict__ gqg, const float* __restrict__ gqb,
    const float* __restrict__ gkg, const float* __restrict__ gkb,
    const float* __restrict__ gvg, const float* __restrict__ gvb) {
    int idx = blockIdx.x * 256 + threadIdx.x;
    int n = idx & 1023, c = (idx >> 10) & 127, b = idx >> 17;
    int g = c >> 2, dd = c & 3;
    int t = n >> 8, y = (n >> 4) & 15, xq = n & 15;
    int base = t * 4096 + (y << 2) * 64 + (xq << 2);

    const float* zq = &g_z[0][b][c][0];
    const float* zk = &g_z[1][b][c][0];
    const float* zv = &g_z[2][b][c][0];
    float mq = g_mean[0][b][g], rq = g_rstd[0][b][g];
    float mk = g_mean[1][b][g], rk = g_rstd[1][b][g];
    float mv = g_mean[2][b][g], rv = g_rstd[2][b][g];
    float av = rv * gvg[c], bv = gvb[c] - mv * av;

    float sq = 0.f, sk = 0.f;
#pragma unroll
    for (int sy = 0; sy < 4; sy++)
#pragma unroll
        for (int sx = 0; sx < 4; sx++) {
            int off = base + sy * 64 + sx;
            sq += zq[off];
            sk += zk[off];
            g_vp[b][g][n][(dd << 4) + (sy << 2) + sx] = fmaf(zv[off], av, bv);
        }
    float aq = rq * gqg[c];
    g_qp[b][g][n][dd] = fmaf(sq * 0.0625f, aq, gqb[c] - mq * aq);
    float ak = rk * gkg[c];
    g_kp[b][g][n][dd] = fmaf(sk * 0.0625f, ak, gkb[c] - mk * ak);
}

// ================= K4: fused patch attention ==============================
// CTA = (b, head, 128-row tile); 2 threads per row (m split in halves);
// online softmax w/ chunk-level max exchange; AV via fma.rn.f32x2.
// smem float offsets:
#define SM_TAB  0
#define SM_Q    6728
#define SM_ROWC (6728 + 512)
#define SM_K    (6728 + 512 + 128)
#define SM_KC   (6728 + 512 + 128 + 512)
#define SM_V    (6728 + 512 + 128 + 512 + 128)
#define ATTN_SMEM_BYTES ((SM_V + 128 * 64) * 4)

__global__ __launch_bounds__(256, 2) void attn_kernel(
    const float* __restrict__ rel_table, float* __restrict__ out) {
    extern __shared__ float sm[];
    float*  tab  = sm + SM_TAB;
    float4* qs4  = (float4*)(sm + SM_Q);
    int*    rowc = (int*)(sm + SM_ROWC);
    float4* ks4  = (float4*)(sm + SM_K);
    int*    kc   = (int*)(sm + SM_KC);
    float*  vs   = sm + SM_V;

    const int b = blockIdx.z, g = blockIdx.y;
    const int n0 = blockIdx.x << 7;
    const int tid = threadIdx.x;

    for (int i = tid; i < TABSZ; i += 256) tab[i] = rel_table[g * TABSZ + i];
    for (int r = tid; r < 128; r += 256) {
        int n = n0 + r;
        qs4[r]  = *(const float4*)&g_qp[b][g][n][0];
        rowc[r] = 961 * (n >> 8) + 31 * ((n >> 4) & 15) + (n & 15) + 3363;
    }
    __syncthreads();

    const int row = tid >> 1, half = tid & 1;
    const int n = n0 + row;
    const float4 q = qs4[row];
    const int cn = rowc[row];
    const int mb = half << 6;

    float mrun = -1e30f, lsum = 0.f;
    unsigned long long acc[32];
#pragma unroll
    for (int k = 0; k < 32; k++) acc[k] = 0ull;

    for (int mc = 0; mc < 8; mc++) {
        __syncthreads();
        const int m0 = mc << 7;
        if (tid < 128) {
            int m = m0 + tid;
            ks4[tid] = *(const float4*)&g_kp[b][g][m][0];
            kc[tid]  = 961 * (m >> 8) + 31 * ((m >> 4) & 15) + (m & 15);
        }
        {
            const float4* src = (const float4*)&g_vp[b][g][m0][0];
            float4* dst = (float4*)vs;
            for (int i = tid; i < 2048; i += 256) dst[i] = src[i];
        }
        __syncthreads();

        // pass 1: chunk max over my 64 m
        float cmax = -1e30f;
#pragma unroll 4
        for (int mi = 0; mi < 64; mi++) {
            int m = mb + mi;
            float4 kk = ks4[m];
            float l = fmaf(q.x, kk.x, fmaf(q.y, kk.y, fmaf(q.z, kk.z, q.w * kk.w)));
            l = fmaf(l, 0.5f, tab[cn - kc[m]]);
            cmax = fmaxf(cmax, l);
        }
        cmax = fmaxf(cmax, __shfl_xor_sync(0xffffffffu, cmax, 1));
        float mnew = fmaxf(mrun, cmax);
        float corr = __expf(mrun - mnew);
        mrun = mnew;
        lsum *= corr;
        unsigned long long c2 = packf2(corr);
#pragma unroll
        for (int k = 0; k < 32; k++) fmul2(acc[k], c2);

        // pass 2: recompute logits, exp, accumulate AV (f32x2)
#pragma unroll 2
        for (int mi = 0; mi < 64; mi++) {
            int m = mb + mi;
            float4 kk = ks4[m];
            float l = fmaf(q.x, kk.x, fmaf(q.y, kk.y, fmaf(q.z, kk.z, q.w * kk.w)));
            l = fmaf(l, 0.5f, tab[cn - kc[m]]);
            float wgt = __expf(l - mrun);
            lsum += wgt;
            unsigned long long wp = packf2(wgt);
            const ulonglong2* vr = (const ulonglong2*)&vs[m << 6];
#pragma unroll
            for (int k2 = 0; k2 < 16; k2++) {
                ulonglong2 vv = vr[k2];
                ffma2(acc[2 * k2],     wp, vv.x);
                ffma2(acc[2 * k2 + 1], wp, vv.y);
            }
        }
    }

    float ltot = lsum + __shfl_xor_sync(0xffffffffu, lsum, 1);
    float inv = 1.f / ltot;

    const int t = n >> 8, y = (n >> 4) & 15, xq = n & 15;
    size_t obase = ((size_t)(b * C_) + (g << 2)) * S_ + t * 4096 + (y << 2) * 64 + (xq << 2);
    const int klo = half << 4;
#pragma unroll
    for (int k = 0; k < 32; k++) {
        unsigned long long other = __shfl_xor_sync(0xffffffffu, acc[k], 1);
        if (k >= klo && k < klo + 16) {
            float2 a  = *(float2*)&acc[k];
            float2 o2 = *(float2*)&other;
            float2 res = make_float2((a.x + o2.x) * inv, (a.y + o2.y) * inv);
            int j = k << 1;
            int dd = j >> 4, sy = (j >> 2) & 3, sx = j & 3;
            *(float2*)&out[obase + (size_t)dd * S_ + sy * 64 + sx] = res;
        }
    }
}

// ================= launch ==================================================
extern "C" void kernel_launch(void* const* d_in, const int* in_sizes, int n_in,
                              void* d_out, int out_size) {
    const float* x   = (const float*)d_in[0];
    const float* Wq  = (const float*)d_in[1];
    const float* Wk  = (const float*)d_in[2];
    const float* Wv  = (const float*)d_in[3];
    const float* gqg = (const float*)d_in[4];
    const float* gqb = (const float*)d_in[5];
    const float* gkg = (const float*)d_in[6];
    const float* gkb = (const float*)d_in[7];
    const float* gvg = (const float*)d_in[8];
    const float* gvb = (const float*)d_in[9];
    const float* rel_table = (const float*)d_in[10];
    // d_in[11] = rel_index: unused (computed analytically in-kernel)
    float* out = (float*)d_out;

    cudaFuncSetAttribute(proj_kernel, cudaFuncAttributeMaxDynamicSharedMemorySize,
                         PROJ_SMEM_BYTES);
    cudaFuncSetAttribute(attn_kernel, cudaFuncAttributeMaxDynamicSharedMemorySize,
                         ATTN_SMEM_BYTES);

    proj_kernel<<<dim3(128, 2, 3), 256, PROJ_SMEM_BYTES>>>(x, Wq, Wk, Wv);
    stats_kernel<<<dim3(32, 2, 3), 256>>>();
    prep_kernel<<<1024, 256>>>(gqg, gqb, gkg, gkb, gvg, gvb);
    attn_kernel<<<dim3(8, 32, 2), 256, ATTN_SMEM_BYTES>>>(rel_table, out);
}

// round 2
// speedup vs baseline: 1.8979x; 1.8979x over previous
#include <cuda_runtime.h>

// Problem constants
#define B_    2
#define C_    128
#define T_    4
#define S_    16384      // T*H*W
#define NH_   32
#define N_    1024       // T*h*w = 4*16*16
#define TABSZ 6727       // (2T-1)*(2h-1)*(2w-1) = 7*31*31
#define EPS_  1e-5f

// ---------------- scratch (static device globals; no runtime alloc) -------
__device__ float g_z[3][B_][C_][S_];        // q,k,v projections (50.3 MB)
__device__ float g_stat[3][B_][32][2];      // groupnorm sum / sumsq partials
__device__ float g_mean[3][B_][32];
__device__ float g_rstd[3][B_][32];
__device__ float g_qp[B_][NH_][N_][4];      // pooled, normalized Q
__device__ float g_kp[B_][NH_][N_][4];      // pooled, normalized K
__device__ float g_vp[B_][NH_][N_][64];     // normalized V, [m][d*16+p]

// ---------------- f32x2 helpers (B300 2x fp32 path) -----------------------
__device__ __forceinline__ unsigned long long packf2(float v) {
    unsigned long long r; unsigned int u = __float_as_uint(v);
    asm("mov.b64 %0, {%1, %1};" : "=l"(r) : "r"(u));
    return r;
}
__device__ __forceinline__ void ffma2(unsigned long long& d,
                                      unsigned long long a, unsigned long long b) {
    asm("fma.rn.f32x2 %0, %1, %2, %0;" : "+l"(d) : "l"(a), "l"(b));
}
__device__ __forceinline__ void fmul2(unsigned long long& d, unsigned long long a) {
    asm("mul.rn.f32x2 %0, %0, %1;" : "+l"(d) : "l"(a));
}

// ================= K0: zero stat accumulators ==============================
__global__ void zero_stats() {
    ((float*)g_stat)[threadIdx.x] = 0.f;   // 384 threads
}

// ================= K1: 1x1x1 projections (SGEMM 128 x 16384 x 128) =========
// grid (S_/128, B_, 3), block 256, dynamic smem = (128*129 + 128*128)*4 B
// also accumulates per-group sum/sumsq partials via atomicAdd.
#define PROJ_SMEM_BYTES ((128*129 + 128*128) * 4)

__global__ __launch_bounds__(256) void proj_kernel(
    const float* __restrict__ x, const float* __restrict__ Wq,
    const float* __restrict__ Wk, const float* __restrict__ Wv) {
    extern __shared__ float sm[];
    float* Wt = sm;                 // [c][o], row pitch 129 (conflict-free)
    float* Xs = sm + 128 * 129;     // [c][sj], row pitch 128

    const int pr = blockIdx.z;
    const float* Wsel = (pr == 0) ? Wq : ((pr == 1) ? Wk : Wv);
    const int b  = blockIdx.y;
    const int s0 = blockIdx.x << 7;
    const int tid = threadIdx.x;
    const float* xb = x + (size_t)b * C_ * S_;

    for (int i = tid; i < 16384; i += 256) {          // W transpose load
        int o = i >> 7, c = i & 127;
        Wt[c * 129 + o] = Wsel[i];
    }
    for (int i = tid; i < 16384; i += 256) {          // X tile load (coalesced)
        int c = i >> 7, sj = i & 127;
        Xs[(c << 7) + sj] = xb[c * S_ + s0 + sj];
    }
    __syncthreads();

    const int ty = tid >> 4, tx = tid & 15;
    const int ob = ty << 3, sb = tx << 3;
    float acc[8][8];
#pragma unroll
    for (int i = 0; i < 8; i++)
#pragma unroll
        for (int j = 0; j < 8; j++) acc[i][j] = 0.f;

#pragma unroll 4
    for (int c = 0; c < 128; c++) {
        float a[8];
#pragma unroll
        for (int i = 0; i < 8; i++) a[i] = Wt[c * 129 + ob + i];
        float4 b0 = *(const float4*)&Xs[(c << 7) + sb];
        float4 b1 = *(const float4*)&Xs[(c << 7) + sb + 4];
        float bf[8] = {b0.x, b0.y, b0.z, b0.w, b1.x, b1.y, b1.z, b1.w};
#pragma unroll
        for (int i = 0; i < 8; i++)
#pragma unroll
            for (int j = 0; j < 8; j++) acc[i][j] = fmaf(a[i], bf[j], acc[i][j]);
    }
#pragma unroll
    for (int i = 0; i < 8; i++) {
        float* dst = &g_z[pr][b][ob + i][s0 + sb];
        *(float4*)dst       = make_float4(acc[i][0], acc[i][1], acc[i][2], acc[i][3]);
        *(float4*)(dst + 4) = make_float4(acc[i][4], acc[i][5], acc[i][6], acc[i][7]);
    }

    // ---- fused GroupNorm partial stats (channels ob..ob+7 = groups 2ty,2ty+1)
    __syncthreads();              // done reading Wt/Xs; reuse smem
#pragma unroll
    for (int g2 = 0; g2 < 2; g2++) {
        float s = 0.f, s2 = 0.f;
#pragma unroll
        for (int i = 0; i < 4; i++)
#pragma unroll
            for (int j = 0; j < 8; j++) {
                float v = acc[g2 * 4 + i][j];
                s += v; s2 = fmaf(v, v, s2);
            }
        sm[(tid << 2) + (g2 << 1) + 0] = s;
        sm[(tid << 2) + (g2 << 1) + 1] = s2;
    }
    __syncthreads();
    if (tid < 64) {
        int grp = tid >> 1, v = tid & 1;
        int gy = grp >> 1, g2 = grp & 1;
        float r = 0.f;
#pragma unroll
        for (int txx = 0; txx < 16; txx++)
            r += sm[(((gy << 4) + txx) << 2) + (g2 << 1) + v];
        atomicAdd(&g_stat[pr][b][grp][v], r);
    }
}

// ================= K2: finalize stats ======================================
__global__ void finalize_stats() {     // <<<1, 192>>>
    int i = threadIdx.x;
    int pr = i >> 6, r = i & 63, b = r >> 5, grp = r & 31;
    float s  = g_stat[pr][b][grp][0];
    float s2 = g_stat[pr][b][grp][1];
    float mean = s * (1.f / 65536.f);
    float var  = s2 * (1.f / 65536.f) - mean * mean;
    g_mean[pr][b][grp] = mean;
    g_rstd[pr][b][grp] = rsqrtf(var + EPS_);
}

// ================= K3: normalize + pool + patch permute ====================
__global__ __launch_bounds__(256) void prep_kernel(
    const float* __restrict__ gqg, const float* __restrict__ gqb,
    const float* __restrict__ gkg, const float* __restrict__ gkb,
    const float* __restrict__ gvg, const float* __restrict__ gvb) {
    int idx = blockIdx.x * 256 + threadIdx.x;
    int n = idx & 1023, c = (idx >> 10) & 127, b = idx >> 17;
    int g = c >> 2, dd = c & 3;
    int t = n >> 8, y = (n >> 4) & 15, xq = n & 15;
    int base = t * 4096 + (y << 2) * 64 + (xq << 2);

    const float* zq = &g_z[0][b][c][0];
    const float* zk = &g_z[1][b][c][0];
    const float* zv = &g_z[2][b][c][0];
    float mq = g_mean[0][b][g], rq = g_rstd[0][b][g];
    float mk = g_mean[1][b][g], rk = g_rstd[1][b][g];
    float mv = g_mean[2][b][g], rv = g_rstd[2][b][g];
    float av = rv * gvg[c], bv = gvb[c] - mv * av;

    float sq = 0.f, sk = 0.f;
#pragma unroll
    for (int sy = 0; sy < 4; sy++)
#pragma unroll
        for (int sx = 0; sx < 4; sx++) {
            int off = base + sy * 64 + sx;
            sq += zq[off];
            sk += zk[off];
            g_vp[b][g][n][(dd << 4) + (sy << 2) + sx] = fmaf(zv[off], av, bv);
        }
    float aq = rq * gqg[c];
    g_qp[b][g][n][dd] = fmaf(sq * 0.0625f, aq, gqb[c] - mq * aq);
    float ak = rk * gkg[c];
    g_kp[b][g][n][dd] = fmaf(sk * 0.0625f, ak, gkb[c] - mk * ak);
}

// ================= K4: fused patch attention (register-tiled AV) ===========
// CTA = (b, head, 128-row tile). Chunks of 64 keys.
// Stage A (logit role): thread = (row, mseg); computes 32 logits in regs,
//   pair-shfl row max, exp -> smem weights ls[m][row] (pitch 144).
// Stage B (AV role): thread = (rowg, colg); 4-row x 8-col register tile,
//   per m: 1 LDS.128 weights + 2 LDS.128 V -> 16 FFMA2.
#define LP_   144                       // ls pitch (floats), conflict-free
#define SM_TAB   0
#define SM_LS    6728                   // 64 * 144 = 9216
#define SM_VS    (6728 + 9216)          // 64 * 64  = 4096
#define SM_KS    (SM_VS + 4096)         // 64 float4 = 256 floats
#define SM_KC    (SM_KS + 256)          // 64 ints
#define SM_ROWM  (SM_KC + 64)           // 128
#define SM_CORR  (SM_ROWM + 128)        // 128
#define SM_LSUM  (SM_CORR + 128)        // 128
#define ATTN_SMEM_FLOATS (SM_LSUM + 128)
#define ATTN_SMEM_BYTES (ATTN_SMEM_FLOATS * 4)

__global__ __launch_bounds__(256, 2) void attn_kernel(
    const float* __restrict__ rel_table, float* __restrict__ out) {
    extern __shared__ float sm[];
    float*  tab  = sm + SM_TAB;
    float*  ls   = sm + SM_LS;
    float*  vs   = sm + SM_VS;
    float4* ks4  = (float4*)(sm + SM_KS);
    int*    kc   = (int*)(sm + SM_KC);
    float*  rowm = sm + SM_ROWM;
    float*  rcor = sm + SM_CORR;
    float*  rlsm = sm + SM_LSUM;

    const int b = blockIdx.z, g = blockIdx.y;
    const int n0 = blockIdx.x << 7;
    const int tid = threadIdx.x;

    for (int i = tid; i < TABSZ; i += 256) tab[i] = rel_table[g * TABSZ + i];
    if (tid < 128) { rowm[tid] = -1e30f; rlsm[tid] = 0.f; }

    // logit role
    const int lrow = tid >> 1, lseg = tid & 1;
    const int nq = n0 + lrow;
    const float4 q = *(const float4*)&g_qp[b][g][nq][0];
    const int cn = 961 * (nq >> 8) + 31 * ((nq >> 4) & 15) + (nq & 15) + 3363;

    // AV role: 4 rows x 8 cols (4 f32x2)
    const int rowg = tid >> 3, colg = tid & 7;
    unsigned long long acc[16];
#pragma unroll
    for (int k = 0; k < 16; k++) acc[k] = 0ull;

    for (int mc = 0; mc < 16; mc++) {
        __syncthreads();                       // prev AV done with ls/vs
        const int m0 = mc << 6;
        if (tid < 64) {
            int m = m0 + tid;
            ks4[tid] = *(const float4*)&g_kp[b][g][m][0];
            kc[tid]  = 961 * (m >> 8) + 31 * ((m >> 4) & 15) + (m & 15);
        }
        {
            const float4* src = (const float4*)&g_vp[b][g][m0][0];
            float4* dst = (float4*)vs;
            for (int i = tid; i < 1024; i += 256) dst[i] = src[i];
        }
        __syncthreads();

        // ---- logits (kept in registers), m = 2*i + lseg (bank-friendly)
        float lv[32];
        float cmax = -1e30f;
#pragma unroll
        for (int i = 0; i < 32; i++) {
            int m = (i << 1) | lseg;
            float4 kk = ks4[m];
            float l = fmaf(q.x, kk.x, fmaf(q.y, kk.y, fmaf(q.z, kk.z, q.w * kk.w)));
            l = fmaf(l, 0.5f, tab[cn - kc[m]]);
            lv[i] = l;
            cmax = fmaxf(cmax, l);
        }
        cmax = fmaxf(cmax, __shfl_xor_sync(0xffffffffu, cmax, 1));
        float mold = rowm[lrow];
        float mnew = fmaxf(mold, cmax);
        float corr = __expf(mold - mnew);
        float csum = 0.f;
#pragma unroll
        for (int i = 0; i < 32; i++) {
            float w = __expf(lv[i] - mnew);
            csum += w;
            ls[((i << 1) | lseg) * LP_ + lrow] = w;
        }
        csum += __shfl_xor_sync(0xffffffffu, csum, 1);
        if (lseg == 0) {
            rowm[lrow] = mnew;
            rcor[lrow] = corr;
            rlsm[lrow] = rlsm[lrow] * corr + csum;
        }
        __syncthreads();

        // ---- AV: rescale then accumulate
        {
            unsigned long long c0 = packf2(rcor[(rowg << 2) + 0]);
            unsigned long long c1 = packf2(rcor[(rowg << 2) + 1]);
            unsigned long long c2 = packf2(rcor[(rowg << 2) + 2]);
            unsigned long long c3 = packf2(rcor[(rowg << 2) + 3]);
#pragma unroll
            for (int j = 0; j < 4; j++) {
                fmul2(acc[j],      c0);
                fmul2(acc[4 + j],  c1);
                fmul2(acc[8 + j],  c2);
                fmul2(acc[12 + j], c3);
            }
        }
        const float* lsp = ls + (rowg << 2);
        const float* vsp = vs + (colg << 3);
#pragma unroll 4
        for (int m = 0; m < 64; m++) {
            float4 w4 = *(const float4*)&lsp[m * LP_];
            unsigned long long w0 = packf2(w4.x), w1 = packf2(w4.y);
            unsigned long long w2 = packf2(w4.z), w3 = packf2(w4.w);
            ulonglong2 va = *(const ulonglong2*)&vsp[m << 6];
            ulonglong2 vb = *(const ulonglong2*)&vsp[(m << 6) + 4];
            ffma2(acc[0],  w0, va.x); ffma2(acc[1],  w0, va.y);
            ffma2(acc[2],  w0, vb.x); ffma2(acc[3],  w0, vb.y);
            ffma2(acc[4],  w1, va.x); ffma2(acc[5],  w1, va.y);
            ffma2(acc[6],  w1, vb.x); ffma2(acc[7],  w1, vb.y);
            ffma2(acc[8],  w2, va.x); ffma2(acc[9],  w2, va.y);
            ffma2(acc[10], w2, vb.x); ffma2(acc[11], w2, vb.y);
            ffma2(acc[12], w3, va.x); ffma2(acc[13], w3, va.y);
            ffma2(acc[14], w3, vb.x); ffma2(acc[15], w3, vb.y);
        }
    }
    __syncthreads();

    // ---- epilogue: divide by lsum, scatter to output layout
#pragma unroll
    for (int r = 0; r < 4; r++) {
        const int row = (rowg << 2) + r;
        const int n = n0 + row;
        const float inv = 1.f / rlsm[row];
        const int t = n >> 8, y = (n >> 4) & 15, xq = n & 15;
        const size_t obase = ((size_t)(b * C_) + (g << 2)) * S_
                           + t * 4096 + (y << 2) * 64 + (xq << 2);
#pragma unroll
        for (int j = 0; j < 4; j++) {
            float2 a = *(float2*)&acc[(r << 2) + j];
            float2 res = make_float2(a.x * inv, a.y * inv);
            int col = (colg << 3) + (j << 1);
            int dd = col >> 4, p = col & 15;
            int sy = p >> 2, sx = p & 3;
            *(float2*)&out[obase + (size_t)dd * S_ + sy * 64 + sx] = res;
        }
    }
}

// ================= launch ==================================================
extern "C" void kernel_launch(void* const* d_in, const int* in_sizes, int n_in,
                              void* d_out, int out_size) {
    const float* x   = (const float*)d_in[0];
    const float* Wq  = (const float*)d_in[1];
    const float* Wk  = (const float*)d_in[2];
    const float* Wv  = (const float*)d_in[3];
    const float* gqg = (const float*)d_in[4];
    const float* gqb = (const float*)d_in[5];
    const float* gkg = (const float*)d_in[6];
    const float* gkb = (const float*)d_in[7];
    const float* gvg = (const float*)d_in[8];
    const float* gvb = (const float*)d_in[9];
    const float* rel_table = (const float*)d_in[10];
    // d_in[11] = rel_index: unused (computed analytically in-kernel)
    float* out = (float*)d_out;

    cudaFuncSetAttribute(proj_kernel, cudaFuncAttributeMaxDynamicSharedMemorySize,
                         PROJ_SMEM_BYTES);
    cudaFuncSetAttribute(attn_kernel, cudaFuncAttributeMaxDynamicSharedMemorySize,
                         ATTN_SMEM_BYTES);

    zero_stats<<<1, 384>>>();
    proj_kernel<<<dim3(128, 2, 3), 256, PROJ_SMEM_BYTES>>>(x, Wq, Wk, Wv);
    finalize_stats<<<1, 192>>>();
    prep_kernel<<<1024, 256>>>(gqg, gqb, gkg, gkb, gvg, gvb);
    attn_kernel<<<dim3(8, 32, 2), 256, ATTN_SMEM_BYTES>>>(rel_table, out);
}

// round 4
// speedup vs baseline: 2.7921x; 1.4711x over previous
#include <cuda_runtime.h>

// Problem constants
#define B_    2
#define C_    128
#define T_    4
#define S_    16384      // T*H*W
#define NH_   32
#define N_    1024       // T*h*w = 4*16*16
#define TABSZ 6727       // (2T-1)*(2h-1)*(2w-1) = 7*31*31
#define EPS_  1e-5f

// ---------------- scratch (static device globals; no runtime alloc) -------
__device__ float g_z[3][B_][C_][S_];        // q,k,v projections (50.3 MB)
__device__ float g_stat[3][B_][32][2];      // groupnorm sum / sumsq partials
__device__ float g_mean[3][B_][32];
__device__ float g_rstd[3][B_][32];
__device__ float g_qp[B_][NH_][N_][4];      // pooled, normalized Q
__device__ float g_kp[B_][NH_][N_][4];      // pooled, normalized K
__device__ float g_vp[B_][NH_][N_][64];     // normalized V, [m][d*16+p]

// ---------------- f32x2 helpers (B300 2x fp32 path) -----------------------
__device__ __forceinline__ unsigned long long packf2(float v) {
    unsigned long long r; unsigned int u = __float_as_uint(v);
    asm("mov.b64 %0, {%1, %1};" : "=l"(r) : "r"(u));
    return r;
}
__device__ __forceinline__ void ffma2(unsigned long long& d,
                                      unsigned long long a, unsigned long long b) {
    asm("fma.rn.f32x2 %0, %1, %2, %0;" : "+l"(d) : "l"(a), "l"(b));
}

// ---------------- cp.async helpers ----------------------------------------
__device__ __forceinline__ void cp16(void* smem, const void* g) {
    unsigned sa = (unsigned)__cvta_generic_to_shared(smem);
    asm volatile("cp.async.cg.shared.global [%0], [%1], 16;" :: "r"(sa), "l"(g));
}
__device__ __forceinline__ void cp_commit() {
    asm volatile("cp.async.commit_group;");
}
__device__ __forceinline__ void cp_wait0() {
    asm volatile("cp.async.wait_group 0;" ::: "memory");
}

// ================= K0: zero stat accumulators ==============================
__global__ void zero_stats() {
    ((float*)g_stat)[threadIdx.x] = 0.f;   // 384 threads
}

// ================= K1: projections, f32x2 SGEMM 128 x 16384 x 128 ==========
// grid (256, B_, 3), block 256; o-tile 128, s-tile 64; 2 CTAs/SM.
#define PJ_PITCH 132
#define PROJ_SMEM_FLOATS (128 * PJ_PITCH + 128 * 64)
#define PROJ_SMEM_BYTES  (PROJ_SMEM_FLOATS * 4)

__global__ __launch_bounds__(256) void proj_kernel(
    const float* __restrict__ x, const float* __restrict__ Wq,
    const float* __restrict__ Wk, const float* __restrict__ Wv) {
    extern __shared__ float sm[];
    float* Wt = sm;                       // [c][o], pitch 132 (16B-aligned rows)
    float* Xs = sm + 128 * PJ_PITCH;      // [c][sj], pitch 64

    const int pr = blockIdx.z;
    const float* Wsel = (pr == 0) ? Wq : ((pr == 1) ? Wk : Wv);
    const int b  = blockIdx.y;
    const int s0 = blockIdx.x << 6;
    const int tid = threadIdx.x;
    const float* xb = x + (size_t)b * C_ * S_;

    for (int i = tid; i < 16384; i += 256) {      // W transpose load
        int o = i >> 7, c = i & 127;
        Wt[c * PJ_PITCH + o] = Wsel[i];
    }
    for (int i = tid; i < 8192; i += 256) {       // X tile (coalesced)
        int c = i >> 6, sj = i & 63;
        Xs[(c << 6) + sj] = xb[c * S_ + s0 + sj];
    }
    __syncthreads();

    const int ty = tid >> 4, tx = tid & 15;
    const int ob = ty << 3, sb = tx << 2;
    unsigned long long acc[4][4];                 // o-pairs x s
#pragma unroll
    for (int i = 0; i < 4; i++)
#pragma unroll
        for (int j = 0; j < 4; j++) acc[i][j] = 0ull;

#pragma unroll 4
    for (int c = 0; c < 128; c++) {
        ulonglong2 alo = *(const ulonglong2*)&Wt[c * PJ_PITCH + ob];
        ulonglong2 ahi = *(const ulonglong2*)&Wt[c * PJ_PITCH + ob + 4];
        float4 bx = *(const float4*)&Xs[(c << 6) + sb];
        unsigned long long b2[4] = {packf2(bx.x), packf2(bx.y),
                                    packf2(bx.z), packf2(bx.w)};
        unsigned long long a2[4] = {alo.x, alo.y, ahi.x, ahi.y};
#pragma unroll
        for (int op = 0; op < 4; op++)
#pragma unroll
            for (int s = 0; s < 4; s++) ffma2(acc[op][s], a2[op], b2[s]);
    }

    // store: each o-pair holds rows (ob+2op, ob+2op+1)
#pragma unroll
    for (int op = 0; op < 4; op++) {
        float2 p0 = *(float2*)&acc[op][0];
        float2 p1 = *(float2*)&acc[op][1];
        float2 p2 = *(float2*)&acc[op][2];
        float2 p3 = *(float2*)&acc[op][3];
        float* d0 = &g_z[pr][b][ob + 2 * op][s0 + sb];
        float* d1 = &g_z[pr][b][ob + 2 * op + 1][s0 + sb];
        *(float4*)d0 = make_float4(p0.x, p1.x, p2.x, p3.x);
        *(float4*)d1 = make_float4(p0.y, p1.y, p2.y, p3.y);
    }

    // ---- fused GroupNorm partial stats (channels ob..ob+7 = groups 2ty,2ty+1)
    __syncthreads();              // done reading Wt/Xs; reuse smem
#pragma unroll
    for (int g2 = 0; g2 < 2; g2++) {
        float s = 0.f, s2 = 0.f;
#pragma unroll
        for (int op = 2 * g2; op < 2 * g2 + 2; op++)
#pragma unroll
            for (int j = 0; j < 4; j++) {
                float2 p = *(float2*)&acc[op][j];
                s += p.x + p.y;
                s2 = fmaf(p.x, p.x, s2); s2 = fmaf(p.y, p.y, s2);
            }
        sm[(tid << 2) + (g2 << 1) + 0] = s;
        sm[(tid << 2) + (g2 << 1) + 1] = s2;
    }
    __syncthreads();
    if (tid < 64) {
        int grp = tid >> 1, v = tid & 1;
        int gy = grp >> 1, g2 = grp & 1;
        float r = 0.f;
#pragma unroll
        for (int txx = 0; txx < 16; txx++)
            r += sm[(((gy << 4) + txx) << 2) + (g2 << 1) + v];
        atomicAdd(&g_stat[pr][b][grp][v], r);
    }
}

// ================= K2: finalize stats ======================================
__global__ void finalize_stats() {     // <<<1, 192>>>
    int i = threadIdx.x;
    int pr = i >> 6, r = i & 63, b = r >> 5, grp = r & 31;
    float s  = g_stat[pr][b][grp][0];
    float s2 = g_stat[pr][b][grp][1];
    float mean = s * (1.f / 65536.f);
    float var  = s2 * (1.f / 65536.f) - mean * mean;
    g_mean[pr][b][grp] = mean;
    g_rstd[pr][b][grp] = rsqrtf(var + EPS_);
}

// ================= K3: normalize + pool + patch permute ====================
__global__ __launch_bounds__(256) void prep_kernel(
    const float* __restrict__ gqg, const float* __restrict__ gqb,
    const float* __restrict__ gkg, const float* __restrict__ gkb,
    const float* __restrict__ gvg, const float* __restrict__ gvb) {
    int idx = blockIdx.x * 256 + threadIdx.x;
    int n = idx & 1023, c = (idx >> 10) & 127, b = idx >> 17;
    int g = c >> 2, dd = c & 3;
    int t = n >> 8, y = (n >> 4) & 15, xq = n & 15;
    int base = t * 4096 + (y << 2) * 64 + (xq << 2);

    const float* zq = &g_z[0][b][c][0];
    const float* zk = &g_z[1][b][c][0];
    const float* zv = &g_z[2][b][c][0];
    float mq = g_mean[0][b][g], rq = g_rstd[0][b][g];
    float mk = g_mean[1][b][g], rk = g_rstd[1][b][g];
    float mv = g_mean[2][b][g], rv = g_rstd[2][b][g];
    float av = rv * gvg[c], bv = gvb[c] - mv * av;

    float sq = 0.f, sk = 0.f;
#pragma unroll
    for (int sy = 0; sy < 4; sy++) {
        int off = base + sy * 64;
        float4 vq = *(const float4*)&zq[off];
        float4 vk = *(const float4*)&zk[off];
        float4 vv = *(const float4*)&zv[off];
        sq += vq.x + vq.y + vq.z + vq.w;
        sk += vk.x + vk.y + vk.z + vk.w;
        float4 r = make_float4(fmaf(vv.x, av, bv), fmaf(vv.y, av, bv),
                               fmaf(vv.z, av, bv), fmaf(vv.w, av, bv));
        *(float4*)&g_vp[b][g][n][(dd << 4) + (sy << 2)] = r;
    }
    float aq = rq * gqg[c];
    g_qp[b][g][n][dd] = fmaf(sq * 0.0625f, aq, gqb[c] - mq * aq);
    float ak = rk * gkg[c];
    g_kp[b][g][n][dd] = fmaf(sk * 0.0625f, ak, gkb[c] - mk * ak);
}

// ================= K4: fused patch attention (bound softmax, 1-pass) =======
// CTA = (b, head, 128-row tile). All 1024 K in smem; V chunks of 64 via
// cp.async. Per chunk: w-phase (row,seg) -> ls[m][row]; AV (rowg,colg) 4x8
// register tile, conflict-free LDS. Softmax uses per-row upper bound
// 0.5*|q|*max|k| + max(bias) instead of running max -> no rescale.
#define LP_   144                       // ls pitch (floats)
#define SM_TAB   0
#define SM_K     6728                   // 1024 float4 = 4096 floats
#define SM_KC    (SM_K + 4096)          // 1024 ints
#define SM_LS    (SM_KC + 1024)         // 64 * 144 = 9216
#define SM_VS    (SM_LS + 9216)         // 64 * 64 = 4096
#define SM_LSUM  (SM_VS + 4096)         // 128
#define SM_RED   (SM_LSUM + 128)        // 16
#define ATTN_SMEM_FLOATS (SM_RED + 16)
#define ATTN_SMEM_BYTES (ATTN_SMEM_FLOATS * 4)

__global__ __launch_bounds__(256, 2) void attn_kernel(
    const float* __restrict__ rel_table, float* __restrict__ out) {
    extern __shared__ float sm[];
    float*  tab  = sm + SM_TAB;
    float4* ks4  = (float4*)(sm + SM_K);
    int*    kc   = (int*)(sm + SM_KC);
    float*  ls   = sm + SM_LS;
    float*  vs   = sm + SM_VS;
    float*  rlsm = sm + SM_LSUM;
    float*  red  = sm + SM_RED;

    const int b = blockIdx.z, g = blockIdx.y;
    const int n0 = blockIdx.x << 7;
    const int tid = threadIdx.x;

    float tmax = -1e30f;
    for (int i = tid; i < TABSZ; i += 256) {
        float v = rel_table[g * TABSZ + i];
        tab[i] = v;
        tmax = fmaxf(tmax, v);
    }
    float knmax = 0.f;
    for (int i = tid; i < 1024; i += 256) {
        float4 kk = *(const float4*)&g_kp[b][g][i][0];
        ks4[i] = kk;
        kc[i]  = 961 * (i >> 8) + 31 * ((i >> 4) & 15) + (i & 15);
        float nn = fmaf(kk.x, kk.x, fmaf(kk.y, kk.y, fmaf(kk.z, kk.z, kk.w * kk.w)));
        knmax = fmaxf(knmax, nn);
    }
    if (tid < 128) rlsm[tid] = 0.f;
#pragma unroll
    for (int o = 16; o; o >>= 1) {
        tmax  = fmaxf(tmax,  __shfl_xor_sync(0xffffffffu, tmax,  o));
        knmax = fmaxf(knmax, __shfl_xor_sync(0xffffffffu, knmax, o));
    }
    int w = tid >> 5;
    if ((tid & 31) == 0) { red[w] = tmax; red[8 + w] = knmax; }
    __syncthreads();
    tmax = red[0]; knmax = red[8];
#pragma unroll
    for (int i = 1; i < 8; i++) {
        tmax = fmaxf(tmax, red[i]); knmax = fmaxf(knmax, red[8 + i]);
    }

    // w-phase identity
    const int lrow = tid >> 1, lseg = tid & 1;
    const int nq = n0 + lrow;
    const float4 q = *(const float4*)&g_qp[b][g][nq][0];
    const float qq = fmaf(q.x, q.x, fmaf(q.y, q.y, fmaf(q.z, q.z, q.w * q.w)));
    const float bound = fmaf(0.5f * sqrtf(qq), sqrtf(knmax), tmax);
    const int cn = 961 * (nq >> 8) + 31 * ((nq >> 4) & 15) + (nq & 15) + 3363;

    // AV identity: 4 rows x 8 cols (cols colg*4..+3 and 32+colg*4..+3)
    const int rowg = tid >> 3, colg = tid & 7;
    const float* lsp  = ls + (rowg << 2);
    const float* vsp1 = vs + (colg << 2);
    const float* vsp2 = vs + 32 + (colg << 2);
    unsigned long long acc[16];
#pragma unroll
    for (int k = 0; k < 16; k++) acc[k] = 0ull;

    for (int mc = 0; mc < 16; mc++) {
        __syncthreads();                       // prev AV done with ls/vs
        const int m0 = mc << 6;
        {   // async V chunk load (overlaps with w-phase)
            const float4* vsrc = (const float4*)&g_vp[b][g][m0][0];
            float4* vdst = (float4*)vs;
#pragma unroll
            for (int j = 0; j < 4; j++)
                cp16(vdst + tid + 256 * j, vsrc + tid + 256 * j);
            cp_commit();
        }
        // ---- w-phase: 32 logits -> exp -> smem (no max pass needed)
        float csum = 0.f;
#pragma unroll 8
        for (int i = 0; i < 32; i++) {
            int m = (i << 1) | lseg;
            float4 kk = ks4[m0 + m];
            float l = fmaf(q.x, kk.x, fmaf(q.y, kk.y, fmaf(q.z, kk.z, q.w * kk.w)));
            l = fmaf(l, 0.5f, tab[cn - kc[m0 + m]]);
            float wgt = __expf(l - bound);
            csum += wgt;
            ls[m * LP_ + lrow] = wgt;
        }
        csum += __shfl_xor_sync(0xffffffffu, csum, 1);
        if (lseg == 0) rlsm[lrow] += csum;
        cp_wait0();
        __syncthreads();

        // ---- AV accumulate (conflict-free LDS)
#pragma unroll 4
        for (int m = 0; m < 64; m++) {
            float4 w4 = *(const float4*)&lsp[m * LP_];
            unsigned long long w0 = packf2(w4.x), w1 = packf2(w4.y);
            unsigned long long w2 = packf2(w4.z), w3 = packf2(w4.w);
            ulonglong2 va = *(const ulonglong2*)&vsp1[m << 6];
            ulonglong2 vb = *(const ulonglong2*)&vsp2[m << 6];
            ffma2(acc[0],  w0, va.x); ffma2(acc[1],  w0, va.y);
            ffma2(acc[2],  w0, vb.x); ffma2(acc[3],  w0, vb.y);
            ffma2(acc[4],  w1, va.x); ffma2(acc[5],  w1, va.y);
            ffma2(acc[6],  w1, vb.x); ffma2(acc[7],  w1, vb.y);
            ffma2(acc[8],  w2, va.x); ffma2(acc[9],  w2, va.y);
            ffma2(acc[10], w2, vb.x); ffma2(acc[11], w2, vb.y);
            ffma2(acc[12], w3, va.x); ffma2(acc[13], w3, va.y);
            ffma2(acc[14], w3, vb.x); ffma2(acc[15], w3, vb.y);
        }
    }

    // ---- epilogue: divide by lsum, scatter to output layout
#pragma unroll
    for (int r = 0; r < 4; r++) {
        const int row = (rowg << 2) + r;
        const int n = n0 + row;
        const float inv = 1.f / rlsm[row];
        const int t = n >> 8, y = (n >> 4) & 15, xq = n & 15;
        const size_t obase = ((size_t)(b * C_) + (g << 2)) * S_
                           + t * 4096 + (y << 2) * 64 + (xq << 2);
#pragma unroll
        for (int j = 0; j < 4; j++) {
            float2 a = *(float2*)&acc[(r << 2) + j];
            float2 res = make_float2(a.x * inv, a.y * inv);
            int col = (j < 2) ? ((colg << 2) + (j << 1))
                              : (32 + (colg << 2) + ((j - 2) << 1));
            int dd = col >> 4, p = col & 15;
            int sy = p >> 2, sx = p & 3;
            *(float2*)&out[obase + (size_t)dd * S_ + sy * 64 + sx] = res;
        }
    }
}

// ================= launch ==================================================
extern "C" void kernel_launch(void* const* d_in, const int* in_sizes, int n_in,
                              void* d_out, int out_size) {
    const float* x   = (const float*)d_in[0];
    const float* Wq  = (const float*)d_in[1];
    const float* Wk  = (const float*)d_in[2];
    const float* Wv  = (const float*)d_in[3];
    const float* gqg = (const float*)d_in[4];
    const float* gqb = (const float*)d_in[5];
    const float* gkg = (const float*)d_in[6];
    const float* gkb = (const float*)d_in[7];
    const float* gvg = (const float*)d_in[8];
    const float* gvb = (const float*)d_in[9];
    const float* rel_table = (const float*)d_in[10];
    // d_in[11] = rel_index: unused (computed analytically in-kernel)
    float* out = (float*)d_out;

    cudaFuncSetAttribute(proj_kernel, cudaFuncAttributeMaxDynamicSharedMemorySize,
                         PROJ_SMEM_BYTES);
    cudaFuncSetAttribute(attn_kernel, cudaFuncAttributeMaxDynamicSharedMemorySize,
                         ATTN_SMEM_BYTES);

    zero_stats<<<1, 384>>>();
    proj_kernel<<<dim3(256, 2, 3), 256, PROJ_SMEM_BYTES>>>(x, Wq, Wk, Wv);
    finalize_stats<<<1, 192>>>();
    prep_kernel<<<1024, 256>>>(gqg, gqb, gkg, gkb, gvg, gvb);
    attn_kernel<<<dim3(8, 32, 2), 256, ATTN_SMEM_BYTES>>>(rel_table, out);
}

// round 5
// speedup vs baseline: 5.2513x; 1.8807x over previous
#include <cuda_runtime.h>

// Problem constants
#define B_    2
#define C_    128
#define T_    4
#define S_    16384      // T*H*W
#define NH_   32
#define N_    1024       // T*h*w = 4*16*16
#define TABSZ 6727       // (2T-1)*(2h-1)*(2w-1) = 7*31*31
#define EPS_  1e-5f

// ---------------- scratch (static device globals; no runtime alloc) -------
__device__ float g_z[3][B_][C_][S_];        // q,k,v projections (50.3 MB)
__device__ float g_stat[3][B_][32][2];      // groupnorm sum / sumsq partials
__device__ float g_mean[3][B_][32];
__device__ float g_rstd[3][B_][32];
__device__ float g_qp[B_][NH_][N_][4];      // pooled, normalized Q
__device__ float g_kp[B_][NH_][N_][4];      // pooled, normalized K
__device__ float g_vp[B_][NH_][N_][64];     // normalized V (tf32-rounded bits)

// ---------------- f32x2 helpers (B300 2x fp32 path) -----------------------
__device__ __forceinline__ unsigned long long packf2(float v) {
    unsigned long long r; unsigned int u = __float_as_uint(v);
    asm("mov.b64 %0, {%1, %1};" : "=l"(r) : "r"(u));
    return r;
}
__device__ __forceinline__ void ffma2(unsigned long long& d,
                                      unsigned long long a, unsigned long long b) {
    asm("fma.rn.f32x2 %0, %1, %2, %0;" : "+l"(d) : "l"(a), "l"(b));
}

// ---------------- tf32 / mma helpers ---------------------------------------
__device__ __forceinline__ unsigned tf32r(float f) {
    unsigned u; asm("cvt.rna.tf32.f32 %0, %1;" : "=r"(u) : "f"(f)); return u;
}
__device__ __forceinline__ void mma_tf32(float* d, unsigned a0, unsigned a1,
                                         unsigned a2, unsigned a3,
                                         unsigned b0, unsigned b1) {
    asm("mma.sync.aligned.m16n8k8.row.col.f32.tf32.tf32.f32 "
        "{%0,%1,%2,%3}, {%4,%5,%6,%7}, {%8,%9}, {%0,%1,%2,%3};"
        : "+f"(d[0]), "+f"(d[1]), "+f"(d[2]), "+f"(d[3])
        : "r"(a0), "r"(a1), "r"(a2), "r"(a3), "r"(b0), "r"(b1));
}

// ---------------- cp.async helpers ----------------------------------------
__device__ __forceinline__ void cp16(void* smem, const void* g) {
    unsigned sa = (unsigned)__cvta_generic_to_shared(smem);
    asm volatile("cp.async.cg.shared.global [%0], [%1], 16;" :: "r"(sa), "l"(g));
}
__device__ __forceinline__ void cp_commit() {
    asm volatile("cp.async.commit_group;");
}
__device__ __forceinline__ void cp_wait0() {
    asm volatile("cp.async.wait_group 0;" ::: "memory");
}
__device__ __forceinline__ void cp_wait1() {
    asm volatile("cp.async.wait_group 1;" ::: "memory");
}

// ================= K0: zero stat accumulators ==============================
__global__ void zero_stats() {
    ((float*)g_stat)[threadIdx.x] = 0.f;   // 384 threads
}

// ================= K1: projections, f32x2 SGEMM 128 x 16384 x 128 ==========
#define PJ_PITCH 132
#define PROJ_SMEM_FLOATS (128 * PJ_PITCH + 128 * 64)
#define PROJ_SMEM_BYTES  (PROJ_SMEM_FLOATS * 4)

__global__ __launch_bounds__(256) void proj_kernel(
    const float* __restrict__ x, const float* __restrict__ Wq,
    const float* __restrict__ Wk, const float* __restrict__ Wv) {
    extern __shared__ float sm[];
    float* Wt = sm;                       // [c][o], pitch 132
    float* Xs = sm + 128 * PJ_PITCH;      // [c][sj], pitch 64

    const int pr = blockIdx.z;
    const float* Wsel = (pr == 0) ? Wq : ((pr == 1) ? Wk : Wv);
    const int b  = blockIdx.y;
    const int s0 = blockIdx.x << 6;
    const int tid = threadIdx.x;
    const float* xb = x + (size_t)b * C_ * S_;

    for (int i = tid; i < 16384; i += 256) {
        int o = i >> 7, c = i & 127;
        Wt[c * PJ_PITCH + o] = Wsel[i];
    }
    for (int i = tid; i < 8192; i += 256) {
        int c = i >> 6, sj = i & 63;
        Xs[(c << 6) + sj] = xb[c * S_ + s0 + sj];
    }
    __syncthreads();

    const int ty = tid >> 4, tx = tid & 15;
    const int ob = ty << 3, sb = tx << 2;
    unsigned long long acc[4][4];
#pragma unroll
    for (int i = 0; i < 4; i++)
#pragma unroll
        for (int j = 0; j < 4; j++) acc[i][j] = 0ull;

#pragma unroll 4
    for (int c = 0; c < 128; c++) {
        ulonglong2 alo = *(const ulonglong2*)&Wt[c * PJ_PITCH + ob];
        ulonglong2 ahi = *(const ulonglong2*)&Wt[c * PJ_PITCH + ob + 4];
        float4 bx = *(const float4*)&Xs[(c << 6) + sb];
        unsigned long long b2[4] = {packf2(bx.x), packf2(bx.y),
                                    packf2(bx.z), packf2(bx.w)};
        unsigned long long a2[4] = {alo.x, alo.y, ahi.x, ahi.y};
#pragma unroll
        for (int op = 0; op < 4; op++)
#pragma unroll
            for (int s = 0; s < 4; s++) ffma2(acc[op][s], a2[op], b2[s]);
    }

#pragma unroll
    for (int op = 0; op < 4; op++) {
        float2 p0 = *(float2*)&acc[op][0];
        float2 p1 = *(float2*)&acc[op][1];
        float2 p2 = *(float2*)&acc[op][2];
        float2 p3 = *(float2*)&acc[op][3];
        float* d0 = &g_z[pr][b][ob + 2 * op][s0 + sb];
        float* d1 = &g_z[pr][b][ob + 2 * op + 1][s0 + sb];
        *(float4*)d0 = make_float4(p0.x, p1.x, p2.x, p3.x);
        *(float4*)d1 = make_float4(p0.y, p1.y, p2.y, p3.y);
    }

    __syncthreads();
#pragma unroll
    for (int g2 = 0; g2 < 2; g2++) {
        float s = 0.f, s2 = 0.f;
#pragma unroll
        for (int op = 2 * g2; op < 2 * g2 + 2; op++)
#pragma unroll
            for (int j = 0; j < 4; j++) {
                float2 p = *(float2*)&acc[op][j];
                s += p.x + p.y;
                s2 = fmaf(p.x, p.x, s2); s2 = fmaf(p.y, p.y, s2);
            }
        sm[(tid << 2) + (g2 << 1) + 0] = s;
        sm[(tid << 2) + (g2 << 1) + 1] = s2;
    }
    __syncthreads();
    if (tid < 64) {
        int grp = tid >> 1, v = tid & 1;
        int gy = grp >> 1, g2 = grp & 1;
        float r = 0.f;
#pragma unroll
        for (int txx = 0; txx < 16; txx++)
            r += sm[(((gy << 4) + txx) << 2) + (g2 << 1) + v];
        atomicAdd(&g_stat[pr][b][grp][v], r);
    }
}

// ================= K2: finalize stats ======================================
__global__ void finalize_stats() {     // <<<1, 192>>>
    int i = threadIdx.x;
    int pr = i >> 6, r = i & 63, b = r >> 5, grp = r & 31;
    float s  = g_stat[pr][b][grp][0];
    float s2 = g_stat[pr][b][grp][1];
    float mean = s * (1.f / 65536.f);
    float var  = s2 * (1.f / 65536.f) - mean * mean;
    g_mean[pr][b][grp] = mean;
    g_rstd[pr][b][grp] = rsqrtf(var + EPS_);
}

// ================= K3: normalize + pool + patch permute ====================
// V is stored tf32-rounded (bits in float container) for the tensor-core AV.
__global__ __launch_bounds__(256) void prep_kernel(
    const float* __restrict__ gqg, const float* __restrict__ gqb,
    const float* __restrict__ gkg, const float* __restrict__ gkb,
    const float* __restrict__ gvg, const float* __restrict__ gvb) {
    int idx = blockIdx.x * 256 + threadIdx.x;
    int n = idx & 1023, c = (idx >> 10) & 127, b = idx >> 17;
    int g = c >> 2, dd = c & 3;
    int t = n >> 8, y = (n >> 4) & 15, xq = n & 15;
    int base = t * 4096 + (y << 2) * 64 + (xq << 2);

    const float* zq = &g_z[0][b][c][0];
    const float* zk = &g_z[1][b][c][0];
    const float* zv = &g_z[2][b][c][0];
    float mq = g_mean[0][b][g], rq = g_rstd[0][b][g];
    float mk = g_mean[1][b][g], rk = g_rstd[1][b][g];
    float mv = g_mean[2][b][g], rv = g_rstd[2][b][g];
    float av = rv * gvg[c], bv = gvb[c] - mv * av;

    float sq = 0.f, sk = 0.f;
#pragma unroll
    for (int sy = 0; sy < 4; sy++) {
        int off = base + sy * 64;
        float4 vq = *(const float4*)&zq[off];
        float4 vk = *(const float4*)&zk[off];
        float4 vv = *(const float4*)&zv[off];
        sq += vq.x + vq.y + vq.z + vq.w;
        sk += vk.x + vk.y + vk.z + vk.w;
        float4 r = make_float4(
            __uint_as_float(tf32r(fmaf(vv.x, av, bv))),
            __uint_as_float(tf32r(fmaf(vv.y, av, bv))),
            __uint_as_float(tf32r(fmaf(vv.z, av, bv))),
            __uint_as_float(tf32r(fmaf(vv.w, av, bv))));
        *(float4*)&g_vp[b][g][n][(dd << 4) + (sy << 2)] = r;
    }
    float aq = rq * gqg[c];
    g_qp[b][g][n][dd] = fmaf(sq * 0.0625f, aq, gqb[c] - mq * aq);
    float ak = rk * gkg[c];
    g_kp[b][g][n][dd] = fmaf(sk * 0.0625f, ak, gkb[c] - mk * ak);
}

// ================= K4: fused tensor-core patch attention ===================
// CTA = (b, head, 128 rows). Warp owns 16 rows x all 64 cols.
// Per k8 step: each thread computes its own 4 logits (= its m16n8k8 A-frag
// slots), exps in fp32 (row-sum), converts to tf32, MMA against V B-frags
// from a 3-deep cp.async smem ring (pitch 72 => conflict-free B loads).
// Bound-softmax: weight = exp(logit - rowbound), normalized exactly at end.
#define VSP_    72
#define VS_BUF  (64 * VSP_)                 // 4608 floats per stage
#define SM_TAB  0
#define SM_K    6728                        // 1024 float4
#define SM_KC   (SM_K + 4096)               // 1024 ints
#define SM_VS   (SM_KC + 1024)              // 3 * 4608
#define SM_RED  (SM_VS + 3 * VS_BUF)        // 16
#define ATTN_SMEM_FLOATS (SM_RED + 16)
#define ATTN_SMEM_BYTES (ATTN_SMEM_FLOATS * 4)

__global__ __launch_bounds__(256, 2) void attn_kernel(
    const float* __restrict__ rel_table, float* __restrict__ out) {
    extern __shared__ float sm[];
    float*  tab  = sm + SM_TAB;
    float4* ks4  = (float4*)(sm + SM_K);
    int*    kc   = (int*)(sm + SM_KC);
    float*  vsb0 = sm + SM_VS;
    float*  red  = sm + SM_RED;

    const int b = blockIdx.z, g = blockIdx.y;
    const int n0 = blockIdx.x << 7;
    const int tid = threadIdx.x;

    // ---- kick off V chunks 0 and 1 immediately (independent of smem init)
#pragma unroll
    for (int st = 0; st < 2; st++) {
        const float4* vsrc = (const float4*)&g_vp[b][g][st << 6][0];
        float* vdst = vsb0 + st * VS_BUF;
#pragma unroll
        for (int j = 0; j < 4; j++) {
            int idx = tid + 256 * j;
            int row = idx >> 4, seg = idx & 15;
            cp16(vdst + row * VSP_ + seg * 4, (const float*)vsrc + row * 64 + seg * 4);
        }
        cp_commit();
    }

    // ---- load bias table, K, kc; reduce tmax / knmax
    float tmax = -1e30f;
    for (int i = tid; i < TABSZ; i += 256) {
        float v = rel_table[g * TABSZ + i];
        tab[i] = v;
        tmax = fmaxf(tmax, v);
    }
    float knmax = 0.f;
    for (int i = tid; i < 1024; i += 256) {
        float4 kk = *(const float4*)&g_kp[b][g][i][0];
        ks4[i] = kk;
        kc[i]  = 961 * (i >> 8) + 31 * ((i >> 4) & 15) + (i & 15);
        float nn = fmaf(kk.x, kk.x, fmaf(kk.y, kk.y, fmaf(kk.z, kk.z, kk.w * kk.w)));
        knmax = fmaxf(knmax, nn);
    }
#pragma unroll
    for (int o = 16; o; o >>= 1) {
        tmax  = fmaxf(tmax,  __shfl_xor_sync(0xffffffffu, tmax,  o));
        knmax = fmaxf(knmax, __shfl_xor_sync(0xffffffffu, knmax, o));
    }
    int w = tid >> 5;
    if ((tid & 31) == 0) { red[w] = tmax; red[8 + w] = knmax; }
    __syncthreads();
    tmax = red[0]; knmax = red[8];
#pragma unroll
    for (int i = 1; i < 8; i++) {
        tmax = fmaxf(tmax, red[i]); knmax = fmaxf(knmax, red[8 + i]);
    }
    const float kn = sqrtf(knmax);

    // ---- per-thread identity (mma fragment coordinates)
    const int warp = tid >> 5, lane = tid & 31;
    const int gid = lane >> 2, tg = lane & 3;
    const int r0 = (warp << 4) + gid;          // local row (0..127)
    const int nq0 = n0 + r0, nq1 = nq0 + 8;
    const float4 q0 = *(const float4*)&g_qp[b][g][nq0][0];
    const float4 q1 = *(const float4*)&g_qp[b][g][nq1][0];
    const float qq0 = fmaf(q0.x, q0.x, fmaf(q0.y, q0.y, fmaf(q0.z, q0.z, q0.w * q0.w)));
    const float qq1 = fmaf(q1.x, q1.x, fmaf(q1.y, q1.y, fmaf(q1.z, q1.z, q1.w * q1.w)));
    const float bnd0 = fmaf(0.5f * sqrtf(qq0), kn, tmax);
    const float bnd1 = fmaf(0.5f * sqrtf(qq1), kn, tmax);
    const int cn0 = 961 * (nq0 >> 8) + 31 * ((nq0 >> 4) & 15) + (nq0 & 15) + 3363;
    const int cn1 = 961 * (nq1 >> 8) + 31 * ((nq1 >> 4) & 15) + (nq1 & 15) + 3363;

    float acc[8][4];
#pragma unroll
    for (int j = 0; j < 8; j++)
#pragma unroll
        for (int i = 0; i < 4; i++) acc[j][i] = 0.f;
    float wsum0 = 0.f, wsum1 = 0.f;

    // ---- main loop: 16 chunks of 64 keys, 3-stage cp.async ring
    for (int mc = 0; mc < 16; mc++) {
        if (mc < 15) cp_wait1(); else cp_wait0();
        __syncthreads();                      // chunk mc visible; ring slot free
        if (mc + 2 < 16) {
            const float4* vsrc = (const float4*)&g_vp[b][g][(mc + 2) << 6][0];
            float* vdst = vsb0 + ((mc + 2) % 3) * VS_BUF;
#pragma unroll
            for (int j = 0; j < 4; j++) {
                int idx = tid + 256 * j;
                int row = idx >> 4, seg = idx & 15;
                cp16(vdst + row * VSP_ + seg * 4,
                     (const float*)vsrc + row * 64 + seg * 4);
            }
            cp_commit();
        }
        const float* vsb = vsb0 + (mc % 3) * VS_BUF;
        const int m0 = mc << 6;

#pragma unroll
        for (int sub = 0; sub < 8; sub++) {
            const int mk = m0 + (sub << 3);
            float4 k0 = ks4[mk + tg];
            float4 k1 = ks4[mk + tg + 4];
            int c0i = kc[mk + tg], c1i = kc[mk + tg + 4];

            float d00 = fmaf(q0.x, k0.x, fmaf(q0.y, k0.y, fmaf(q0.z, k0.z, q0.w * k0.w)));
            float d01 = fmaf(q0.x, k1.x, fmaf(q0.y, k1.y, fmaf(q0.z, k1.z, q0.w * k1.w)));
            float d10 = fmaf(q1.x, k0.x, fmaf(q1.y, k0.y, fmaf(q1.z, k0.z, q1.w * k0.w)));
            float d11 = fmaf(q1.x, k1.x, fmaf(q1.y, k1.y, fmaf(q1.z, k1.z, q1.w * k1.w)));

            float w00 = __expf(fmaf(d00, 0.5f, tab[cn0 - c0i]) - bnd0);
            float w01 = __expf(fmaf(d01, 0.5f, tab[cn0 - c1i]) - bnd0);
            float w10 = __expf(fmaf(d10, 0.5f, tab[cn1 - c0i]) - bnd1);
            float w11 = __expf(fmaf(d11, 0.5f, tab[cn1 - c1i]) - bnd1);
            wsum0 += w00 + w01;
            wsum1 += w10 + w11;

            unsigned a0 = tf32r(w00), a1 = tf32r(w10);
            unsigned a2 = tf32r(w01), a3 = tf32r(w11);

            const float* vr0 = vsb + ((sub << 3) + tg) * VSP_ + gid;
            const float* vr1 = vr0 + 4 * VSP_;
#pragma unroll
            for (int j = 0; j < 8; j++) {
                unsigned b0 = __float_as_uint(vr0[8 * j]);
                unsigned b1 = __float_as_uint(vr1[8 * j]);
                mma_tf32(acc[j], a0, a1, a2, a3, b0, b1);
            }
        }
    }

    // ---- exact row sums (fp32) and epilogue
    wsum0 += __shfl_xor_sync(0xffffffffu, wsum0, 1);
    wsum0 += __shfl_xor_sync(0xffffffffu, wsum0, 2);
    wsum1 += __shfl_xor_sync(0xffffffffu, wsum1, 1);
    wsum1 += __shfl_xor_sync(0xffffffffu, wsum1, 2);
    const float inv0 = 1.f / wsum0, inv1 = 1.f / wsum1;

    const int t0 = nq0 >> 8, y0 = (nq0 >> 4) & 15, x0 = nq0 & 15;
    const int t1 = nq1 >> 8, y1 = (nq1 >> 4) & 15, x1 = nq1 & 15;
    const size_t ob0 = ((size_t)(b * C_) + (g << 2)) * S_
                     + t0 * 4096 + (y0 << 2) * 64 + (x0 << 2);
    const size_t ob1 = ((size_t)(b * C_) + (g << 2)) * S_
                     + t1 * 4096 + (y1 << 2) * 64 + (x1 << 2);
#pragma unroll
    for (int j = 0; j < 8; j++) {
        int col = 8 * j + 2 * tg;
        int dd = col >> 4, p = col & 15;
        int sy = p >> 2, sx = p & 3;
        size_t off = (size_t)dd * S_ + sy * 64 + sx;
        *(float2*)&out[ob0 + off] = make_float2(acc[j][0] * inv0, acc[j][1] * inv0);
        *(float2*)&out[ob1 + off] = make_float2(acc[j][2] * inv1, acc[j][3] * inv1);
    }
}

// ================= launch ==================================================
extern "C" void kernel_launch(void* const* d_in, const int* in_sizes, int n_in,
                              void* d_out, int out_size) {
    const float* x   = (const float*)d_in[0];
    const float* Wq  = (const float*)d_in[1];
    const float* Wk  = (const float*)d_in[2];
    const float* Wv  = (const float*)d_in[3];
    const float* gqg = (const float*)d_in[4];
    const float* gqb = (const float*)d_in[5];
    const float* gkg = (const float*)d_in[6];
    const float* gkb = (const float*)d_in[7];
    const float* gvg = (const float*)d_in[8];
    const float* gvb = (const float*)d_in[9];
    const float* rel_table = (const float*)d_in[10];
    // d_in[11] = rel_index: unused (computed analytically in-kernel)
    float* out = (float*)d_out;

    cudaFuncSetAttribute(proj_kernel, cudaFuncAttributeMaxDynamicSharedMemorySize,
                         PROJ_SMEM_BYTES);
    cudaFuncSetAttribute(attn_kernel, cudaFuncAttributeMaxDynamicSharedMemorySize,
                         ATTN_SMEM_BYTES);

    zero_stats<<<1, 384>>>();
    proj_kernel<<<dim3(256, 2, 3), 256, PROJ_SMEM_BYTES>>>(x, Wq, Wk, Wv);
    finalize_stats<<<1, 192>>>();
    prep_kernel<<<1024, 256>>>(gqg, gqb, gkg, gkb, gvg, gvb);
    attn_kernel<<<dim3(8, 32, 2), 256, ATTN_SMEM_BYTES>>>(rel_table, out);
}

// round 6
// speedup vs baseline: 6.3406x; 1.2074x over previous
#include <cuda_runtime.h>

// Problem constants
#define B_    2
#define C_    128
#define T_    4
#define S_    16384      // T*H*W
#define NH_   32
#define N_    1024       // T*h*w = 4*16*16
#define TABSZ 6727       // (2T-1)*(2h-1)*(2w-1) = 7*31*31
#define EPS_  1e-5f

// ---------------- scratch (static device globals; no runtime alloc) -------
__device__ float g_z[3][B_][C_][S_];        // q,k,v projections (50.3 MB)
__device__ float g_stat[3][B_][32][2];      // groupnorm sum / sumsq partials
__device__ float g_mean[3][B_][32];
__device__ float g_rstd[3][B_][32];
__device__ float g_qp[B_][NH_][N_][4];      // pooled, normalized Q
__device__ float g_kp[B_][NH_][N_][4];      // pooled, normalized K
__device__ float g_vp[B_][NH_][N_][64];     // normalized V (tf32-rounded bits)

// ---------------- tf32 / mma helpers ---------------------------------------
__device__ __forceinline__ unsigned tf32r(float f) {
    unsigned u; asm("cvt.rna.tf32.f32 %0, %1;" : "=r"(u) : "f"(f)); return u;
}
__device__ __forceinline__ void mma_tf32(float* d, unsigned a0, unsigned a1,
                                         unsigned a2, unsigned a3,
                                         unsigned b0, unsigned b1) {
    asm("mma.sync.aligned.m16n8k8.row.col.f32.tf32.tf32.f32 "
        "{%0,%1,%2,%3}, {%4,%5,%6,%7}, {%8,%9}, {%0,%1,%2,%3};"
        : "+f"(d[0]), "+f"(d[1]), "+f"(d[2]), "+f"(d[3])
        : "r"(a0), "r"(a1), "r"(a2), "r"(a3), "r"(b0), "r"(b1));
}
// split fp32 into tf32-hi (masked bits) + exact fp32 residual (raw bits,
// truncated to tf32 by the MMA hardware: residual error ~2^-24 of a)
__device__ __forceinline__ void split32(float f, unsigned& hi, unsigned& lo) {
    unsigned u = __float_as_uint(f);
    hi = u & 0xFFFFE000u;
    lo = __float_as_uint(f - __uint_as_float(hi));
}

// ---------------- cp.async helpers ----------------------------------------
__device__ __forceinline__ void cp16(void* smem, const void* g) {
    unsigned sa = (unsigned)__cvta_generic_to_shared(smem);
    asm volatile("cp.async.cg.shared.global [%0], [%1], 16;" :: "r"(sa), "l"(g));
}
__device__ __forceinline__ void cp_commit() {
    asm volatile("cp.async.commit_group;");
}
__device__ __forceinline__ void cp_wait0() {
    asm volatile("cp.async.wait_group 0;" ::: "memory");
}
__device__ __forceinline__ void cp_wait1() {
    asm volatile("cp.async.wait_group 1;" ::: "memory");
}

// ================= K0: zero stat accumulators ==============================
__global__ void zero_stats() {
    ((float*)g_stat)[threadIdx.x] = 0.f;   // 384 threads
}

// ================= K1: projections via 3xTF32 tensor-core GEMM =============
// Per CTA: 128 o x 64 s tile; K=128 in 4 chunks of 32c, double-buffered
// cp.async. Warp = (ow 0..3, sw 0..1): 32 o (2 m16) x 32 s (4 n8).
// Accuracy: a*b ~= ahi*bhi + ahi*blo + alo*bhi  (error ~2^-24).
#define WS_PITCH 36
#define XS_PITCH 72
#define WS_STAGE (128 * WS_PITCH)     // 4608 floats
#define XS_STAGE (32 * XS_PITCH)      // 2304 floats
#define SB_OFF   (2 * WS_STAGE + 2 * XS_STAGE)
#define PROJ_SMEM_FLOATS (SB_OFF + 512)
#define PROJ_SMEM_BYTES  (PROJ_SMEM_FLOATS * 4)

__global__ __launch_bounds__(256, 2) void proj_kernel(
    const float* __restrict__ x, const float* __restrict__ Wq,
    const float* __restrict__ Wk, const float* __restrict__ Wv) {
    extern __shared__ float sm[];
    float* Ws   = sm;                         // [stage][o:128][c:32] pitch 36
    float* Xs   = sm + 2 * WS_STAGE;          // [stage][c:32][s:64] pitch 72
    float* sbuf = sm + SB_OFF;                // 512: stats partials

    const int pr = blockIdx.z;
    const float* Wsel = (pr == 0) ? Wq : ((pr == 1) ? Wk : Wv);
    const int b   = blockIdx.y;
    const int s_t = blockIdx.x << 6;
    const int tid = threadIdx.x;
    const float* xb = x + (size_t)b * C_ * S_;

    // ---- stage issuer: W chunk 128x32 (1024 cp16), X chunk 32x64 (512 cp16)
    auto issue = [&](int kc, int st) {
        float* wd = Ws + st * WS_STAGE;
        float* xd = Xs + st * XS_STAGE;
#pragma unroll
        for (int j = 0; j < 4; j++) {
            int e = tid + 256 * j;
            int o = e >> 3, seg = e & 7;
            cp16(wd + o * WS_PITCH + seg * 4, Wsel + o * 128 + kc * 32 + seg * 4);
        }
#pragma unroll
        for (int j = 0; j < 2; j++) {
            int e = tid + 256 * j;
            int c = e >> 4, seg = e & 15;
            cp16(xd + c * XS_PITCH + seg * 4,
                 xb + (size_t)(kc * 32 + c) * S_ + s_t + seg * 4);
        }
        cp_commit();
    };

    const int warp = tid >> 5, lane = tid & 31;
    const int gid = lane >> 2, tg = lane & 3;
    const int ow = warp >> 1, sw = warp & 1;
    const int o0 = ow << 5;                   // 32 o per warp
    const int sbase = sw << 5;                // 32 s per warp

    float acc[2][4][4];
#pragma unroll
    for (int mb = 0; mb < 2; mb++)
#pragma unroll
        for (int nb = 0; nb < 4; nb++)
#pragma unroll
            for (int i = 0; i < 4; i++) acc[mb][nb][i] = 0.f;

    issue(0, 0);
    for (int kc = 0; kc < 4; kc++) {
        cp_wait0();
        __syncthreads();                      // chunk kc visible to all
        if (kc < 3) issue(kc + 1, (kc + 1) & 1);
        const float* Wb = Ws + (kc & 1) * WS_STAGE;
        const float* Xb = Xs + (kc & 1) * XS_STAGE;

#pragma unroll
        for (int ks = 0; ks < 4; ks++) {
            // B fragments (X): b0=(k=tg, s=gid), b1=(k=tg+4, s=gid)
            unsigned bh[4][2], bl[4][2];
#pragma unroll
            for (int nb = 0; nb < 4; nb++) {
                const float* xp = Xb + (ks * 8 + tg) * XS_PITCH
                                + sbase + nb * 8 + gid;
                split32(xp[0],            bh[nb][0], bl[nb][0]);
                split32(xp[4 * XS_PITCH], bh[nb][1], bl[nb][1]);
            }
#pragma unroll
            for (int mb = 0; mb < 2; mb++) {
                // A fragments (W): a0=(o=gid,k=tg) a1=(gid+8,tg)
                //                  a2=(gid,tg+4)   a3=(gid+8,tg+4)
                const float* wp0 = Wb + (o0 + mb * 16 + gid) * WS_PITCH
                                 + ks * 8 + tg;
                const float* wp1 = wp0 + 8 * WS_PITCH;
                unsigned ah0, ah1, ah2, ah3, al0, al1, al2, al3;
                split32(wp0[0], ah0, al0);
                split32(wp1[0], ah1, al1);
                split32(wp0[4], ah2, al2);
                split32(wp1[4], ah3, al3);
#pragma unroll
                for (int nb = 0; nb < 4; nb++) {
                    mma_tf32(acc[mb][nb], ah0, ah1, ah2, ah3, bh[nb][0], bh[nb][1]);
                    mma_tf32(acc[mb][nb], ah0, ah1, ah2, ah3, bl[nb][0], bl[nb][1]);
                    mma_tf32(acc[mb][nb], al0, al1, al2, al3, bh[nb][0], bh[nb][1]);
                }
            }
        }
        __syncthreads();                      // done reading buf before reuse
    }

    // ---- store D frags: (row, col 2tg/2tg+1) pairs
#pragma unroll
    for (int mb = 0; mb < 2; mb++) {
        const int r0 = o0 + mb * 16 + gid;
#pragma unroll
        for (int nb = 0; nb < 4; nb++) {
            const int sg = s_t + sbase + nb * 8 + (tg << 1);
            *(float2*)&g_z[pr][b][r0][sg]     = make_float2(acc[mb][nb][0], acc[mb][nb][1]);
            *(float2*)&g_z[pr][b][r0 + 8][sg] = make_float2(acc[mb][nb][2], acc[mb][nb][3]);
        }
    }

    // ---- fused GroupNorm partial stats
#pragma unroll
    for (int mb = 0; mb < 2; mb++)
#pragma unroll
        for (int hi = 0; hi < 2; hi++) {
            float s = 0.f, s2 = 0.f;
#pragma unroll
            for (int nb = 0; nb < 4; nb++) {
                float v0 = acc[mb][nb][hi * 2 + 0];
                float v1 = acc[mb][nb][hi * 2 + 1];
                s += v0 + v1;
                s2 = fmaf(v0, v0, s2); s2 = fmaf(v1, v1, s2);
            }
            // reduce over tg (lanes differing in bits 0-1)
            s  += __shfl_xor_sync(0xffffffffu, s, 1);
            s  += __shfl_xor_sync(0xffffffffu, s, 2);
            s2 += __shfl_xor_sync(0xffffffffu, s2, 1);
            s2 += __shfl_xor_sync(0xffffffffu, s2, 2);
            if (tg == 0) {
                int idx = (((warp << 3) | gid) << 3) | (mb << 2) | (hi << 1);
                sbuf[idx]     = s;
                sbuf[idx + 1] = s2;
            }
        }
    __syncthreads();
    if (tid < 64) {
        int grp = tid >> 1, v = tid & 1;
        float tot = 0.f;
#pragma unroll
        for (int ci = 0; ci < 4; ci++) {
            int ch = (grp << 2) + ci;
            int cow = ch >> 5, r = ch & 31;
            int cmb = r >> 4, chi = (r >> 3) & 1, cgid = r & 7;
#pragma unroll
            for (int csw = 0; csw < 2; csw++) {
                int w2 = (cow << 1) | csw;
                tot += sbuf[(((w2 << 3) | cgid) << 3) | (cmb << 2) | (chi << 1) | v];
            }
        }
        atomicAdd(&g_stat[pr][b][grp][v], tot);
    }
}

// ================= K2: finalize stats ======================================
__global__ void finalize_stats() {     // <<<1, 192>>>
    int i = threadIdx.x;
    int pr = i >> 6, r = i & 63, b = r >> 5, grp = r & 31;
    float s  = g_stat[pr][b][grp][0];
    float s2 = g_stat[pr][b][grp][1];
    float mean = s * (1.f / 65536.f);
    float var  = s2 * (1.f / 65536.f) - mean * mean;
    g_mean[pr][b][grp] = mean;
    g_rstd[pr][b][grp] = rsqrtf(var + EPS_);
}

// ================= K3: normalize + pool + patch permute ====================
// V is stored tf32-rounded (bits in float container) for the tensor-core AV.
__global__ __launch_bounds__(256) void prep_kernel(
    const float* __restrict__ gqg, const float* __restrict__ gqb,
    const float* __restrict__ gkg, const float* __restrict__ gkb,
    const float* __restrict__ gvg, const float* __restrict__ gvb) {
    int idx = blockIdx.x * 256 + threadIdx.x;
    int n = idx & 1023, c = (idx >> 10) & 127, b = idx >> 17;
    int g = c >> 2, dd = c & 3;
    int t = n >> 8, y = (n >> 4) & 15, xq = n & 15;
    int base = t * 4096 + (y << 2) * 64 + (xq << 2);

    const float* zq = &g_z[0][b][c][0];
    const float* zk = &g_z[1][b][c][0];
    const float* zv = &g_z[2][b][c][0];
    float mq = g_mean[0][b][g], rq = g_rstd[0][b][g];
    float mk = g_mean[1][b][g], rk = g_rstd[1][b][g];
    float mv = g_mean[2][b][g], rv = g_rstd[2][b][g];
    float av = rv * gvg[c], bv = gvb[c] - mv * av;

    float sq = 0.f, sk = 0.f;
#pragma unroll
    for (int sy = 0; sy < 4; sy++) {
        int off = base + sy * 64;
        float4 vq = *(const float4*)&zq[off];
        float4 vk = *(const float4*)&zk[off];
        float4 vv = *(const float4*)&zv[off];
        sq += vq.x + vq.y + vq.z + vq.w;
        sk += vk.x + vk.y + vk.z + vk.w;
        float4 r = make_float4(
            __uint_as_float(tf32r(fmaf(vv.x, av, bv))),
            __uint_as_float(tf32r(fmaf(vv.y, av, bv))),
            __uint_as_float(tf32r(fmaf(vv.z, av, bv))),
            __uint_as_float(tf32r(fmaf(vv.w, av, bv))));
        *(float4*)&g_vp[b][g][n][(dd << 4) + (sy << 2)] = r;
    }
    float aq = rq * gqg[c];
    g_qp[b][g][n][dd] = fmaf(sq * 0.0625f, aq, gqb[c] - mq * aq);
    float ak = rk * gkg[c];
    g_kp[b][g][n][dd] = fmaf(sk * 0.0625f, ak, gkb[c] - mk * ak);
}

// ================= K4: fused tensor-core patch attention ===================
// CTA = (b, head, 128 rows). Warp owns 16 rows x all 64 cols.
// Per k8 step: each thread computes its own 4 logits (= its m16n8k8 A-frag
// slots), exps in fp32 (row-sum), feeds raw bits (HW tf32 truncation) into
// MMA against V B-frags from a 3-deep cp.async smem ring (pitch 72).
// Bound-softmax: weight = exp(logit - rowbound), normalized exactly at end.
#define VSP_    72
#define VS_BUF  (64 * VSP_)                 // 4608 floats per stage
#define SM_TAB  0
#define SM_K    6728                        // 1024 float4
#define SM_KC   (SM_K + 4096)               // 1024 ints
#define SM_VS   (SM_KC + 1024)              // 3 * 4608
#define SM_RED  (SM_VS + 3 * VS_BUF)        // 16
#define ATTN_SMEM_FLOATS (SM_RED + 16)
#define ATTN_SMEM_BYTES (ATTN_SMEM_FLOATS * 4)

__global__ __launch_bounds__(256, 2) void attn_kernel(
    const float* __restrict__ rel_table, float* __restrict__ out) {
    extern __shared__ float sm[];
    float*  tab  = sm + SM_TAB;
    float4* ks4  = (float4*)(sm + SM_K);
    int*    kc   = (int*)(sm + SM_KC);
    float*  vsb0 = sm + SM_VS;
    float*  red  = sm + SM_RED;

    const int b = blockIdx.z, g = blockIdx.y;
    const int n0 = blockIdx.x << 7;
    const int tid = threadIdx.x;

    // ---- kick off V chunks 0 and 1 immediately (independent of smem init)
#pragma unroll
    for (int st = 0; st < 2; st++) {
        const float4* vsrc = (const float4*)&g_vp[b][g][st << 6][0];
        float* vdst = vsb0 + st * VS_BUF;
#pragma unroll
        for (int j = 0; j < 4; j++) {
            int idx = tid + 256 * j;
            int row = idx >> 4, seg = idx & 15;
            cp16(vdst + row * VSP_ + seg * 4, (const float*)vsrc + row * 64 + seg * 4);
        }
        cp_commit();
    }

    // ---- load bias table, K, kc; reduce tmax / knmax
    float tmax = -1e30f;
    for (int i = tid; i < TABSZ; i += 256) {
        float v = rel_table[g * TABSZ + i];
        tab[i] = v;
        tmax = fmaxf(tmax, v);
    }
    float knmax = 0.f;
    for (int i = tid; i < 1024; i += 256) {
        float4 kk = *(const float4*)&g_kp[b][g][i][0];
        ks4[i] = kk;
        kc[i]  = 961 * (i >> 8) + 31 * ((i >> 4) & 15) + (i & 15);
        float nn = fmaf(kk.x, kk.x, fmaf(kk.y, kk.y, fmaf(kk.z, kk.z, kk.w * kk.w)));
        knmax = fmaxf(knmax, nn);
    }
#pragma unroll
    for (int o = 16; o; o >>= 1) {
        tmax  = fmaxf(tmax,  __shfl_xor_sync(0xffffffffu, tmax,  o));
        knmax = fmaxf(knmax, __shfl_xor_sync(0xffffffffu, knmax, o));
    }
    int w = tid >> 5;
    if ((tid & 31) == 0) { red[w] = tmax; red[8 + w] = knmax; }
    __syncthreads();
    tmax = red[0]; knmax = red[8];
#pragma unroll
    for (int i = 1; i < 8; i++) {
        tmax = fmaxf(tmax, red[i]); knmax = fmaxf(knmax, red[8 + i]);
    }
    const float kn = sqrtf(knmax);

    // ---- per-thread identity (mma fragment coordinates)
    const int warp = tid >> 5, lane = tid & 31;
    const int gid = lane >> 2, tg = lane & 3;
    const int r0 = (warp << 4) + gid;          // local row (0..127)
    const int nq0 = n0 + r0, nq1 = nq0 + 8;
    const float4 q0 = *(const float4*)&g_qp[b][g][nq0][0];
    const float4 q1 = *(const float4*)&g_qp[b][g][nq1][0];
    const float qq0 = fmaf(q0.x, q0.x, fmaf(q0.y, q0.y, fmaf(q0.z, q0.z, q0.w * q0.w)));
    const float qq1 = fmaf(q1.x, q1.x, fmaf(q1.y, q1.y, fmaf(q1.z, q1.z, q1.w * q1.w)));
    const float bnd0 = fmaf(0.5f * sqrtf(qq0), kn, tmax);
    const float bnd1 = fmaf(0.5f * sqrtf(qq1), kn, tmax);
    const int cn0 = 961 * (nq0 >> 8) + 31 * ((nq0 >> 4) & 15) + (nq0 & 15) + 3363;
    const int cn1 = 961 * (nq1 >> 8) + 31 * ((nq1 >> 4) & 15) + (nq1 & 15) + 3363;

    float acc[8][4];
#pragma unroll
    for (int j = 0; j < 8; j++)
#pragma unroll
        for (int i = 0; i < 4; i++) acc[j][i] = 0.f;
    float wsum0 = 0.f, wsum1 = 0.f;

    // ---- main loop: 16 chunks of 64 keys, 3-stage cp.async ring
    for (int mc = 0; mc < 16; mc++) {
        if (mc < 15) cp_wait1(); else cp_wait0();
        __syncthreads();                      // chunk mc visible; ring slot free
        if (mc + 2 < 16) {
            const float4* vsrc = (const float4*)&g_vp[b][g][(mc + 2) << 6][0];
            float* vdst = vsb0 + ((mc + 2) % 3) * VS_BUF;
#pragma unroll
            for (int j = 0; j < 4; j++) {
                int idx = tid + 256 * j;
                int row = idx >> 4, seg = idx & 15;
                cp16(vdst + row * VSP_ + seg * 4,
                     (const float*)vsrc + row * 64 + seg * 4);
            }
            cp_commit();
        }
        const float* vsb = vsb0 + (mc % 3) * VS_BUF;
        const int m0 = mc << 6;

#pragma unroll
        for (int sub = 0; sub < 8; sub++) {
            const int mk = m0 + (sub << 3);
            float4 k0 = ks4[mk + tg];
            float4 k1 = ks4[mk + tg + 4];
            int c0i = kc[mk + tg], c1i = kc[mk + tg + 4];

            float d00 = fmaf(q0.x, k0.x, fmaf(q0.y, k0.y, fmaf(q0.z, k0.z, q0.w * k0.w)));
            float d01 = fmaf(q0.x, k1.x, fmaf(q0.y, k1.y, fmaf(q0.z, k1.z, q0.w * k1.w)));
            float d10 = fmaf(q1.x, k0.x, fmaf(q1.y, k0.y, fmaf(q1.z, k0.z, q1.w * k0.w)));
            float d11 = fmaf(q1.x, k1.x, fmaf(q1.y, k1.y, fmaf(q1.z, k1.z, q1.w * k1.w)));

            float w00 = __expf(fmaf(d00, 0.5f, tab[cn0 - c0i]) - bnd0);
            float w01 = __expf(fmaf(d01, 0.5f, tab[cn0 - c1i]) - bnd0);
            float w10 = __expf(fmaf(d10, 0.5f, tab[cn1 - c0i]) - bnd1);
            float w11 = __expf(fmaf(d11, 0.5f, tab[cn1 - c1i]) - bnd1);
            wsum0 += w00 + w01;
            wsum1 += w10 + w11;

            // raw fp32 bits -> HW tf32 truncation (skips cvt chain)
            unsigned a0 = __float_as_uint(w00), a1 = __float_as_uint(w10);
            unsigned a2 = __float_as_uint(w01), a3 = __float_as_uint(w11);

            const float* vr0 = vsb + ((sub << 3) + tg) * VSP_ + gid;
            const float* vr1 = vr0 + 4 * VSP_;
#pragma unroll
            for (int j = 0; j < 8; j++) {
                unsigned b0 = __float_as_uint(vr0[8 * j]);
                unsigned b1 = __float_as_uint(vr1[8 * j]);
                mma_tf32(acc[j], a0, a1, a2, a3, b0, b1);
            }
        }
    }

    // ---- exact row sums (fp32) and epilogue
    wsum0 += __shfl_xor_sync(0xffffffffu, wsum0, 1);
    wsum0 += __shfl_xor_sync(0xffffffffu, wsum0, 2);
    wsum1 += __shfl_xor_sync(0xffffffffu, wsum1, 1);
    wsum1 += __shfl_xor_sync(0xffffffffu, wsum1, 2);
    const float inv0 = 1.f / wsum0, inv1 = 1.f / wsum1;

    const int t0 = nq0 >> 8, y0 = (nq0 >> 4) & 15, x0 = nq0 & 15;
    const int t1 = nq1 >> 8, y1 = (nq1 >> 4) & 15, x1 = nq1 & 15;
    const size_t ob0 = ((size_t)(b * C_) + (g << 2)) * S_
                     + t0 * 4096 + (y0 << 2) * 64 + (x0 << 2);
    const size_t ob1 = ((size_t)(b * C_) + (g << 2)) * S_
                     + t1 * 4096 + (y1 << 2) * 64 + (x1 << 2);
#pragma unroll
    for (int j = 0; j < 8; j++) {
        int col = 8 * j + 2 * tg;
        int dd = col >> 4, p = col & 15;
        int sy = p >> 2, sx = p & 3;
        size_t off = (size_t)dd * S_ + sy * 64 + sx;
        *(float2*)&out[ob0 + off] = make_float2(acc[j][0] * inv0, acc[j][1] * inv0);
        *(float2*)&out[ob1 + off] = make_float2(acc[j][2] * inv1, acc[j][3] * inv1);
    }
}

// ================= launch ==================================================
extern "C" void kernel_launch(void* const* d_in, const int* in_sizes, int n_in,
                              void* d_out, int out_size) {
    const float* x   = (const float*)d_in[0];
    const float* Wq  = (const float*)d_in[1];
    const float* Wk  = (const float*)d_in[2];
    const float* Wv  = (const float*)d_in[3];
    const float* gqg = (const float*)d_in[4];
    const float* gqb = (const float*)d_in[5];
    const float* gkg = (const float*)d_in[6];
    const float* gkb = (const float*)d_in[7];
    const float* gvg = (const float*)d_in[8];
    const float* gvb = (const float*)d_in[9];
    const float* rel_table = (const float*)d_in[10];
    // d_in[11] = rel_index: unused (computed analytically in-kernel)
    float* out = (float*)d_out;

    cudaFuncSetAttribute(proj_kernel, cudaFuncAttributeMaxDynamicSharedMemorySize,
                         PROJ_SMEM_BYTES);
    cudaFuncSetAttribute(attn_kernel, cudaFuncAttributeMaxDynamicSharedMemorySize,
                         ATTN_SMEM_BYTES);

    zero_stats<<<1, 384>>>();
    proj_kernel<<<dim3(256, 2, 3), 256, PROJ_SMEM_BYTES>>>(x, Wq, Wk, Wv);
    finalize_stats<<<1, 192>>>();
    prep_kernel<<<1024, 256>>>(gqg, gqb, gkg, gkb, gvg, gvb);
    attn_kernel<<<dim3(8, 32, 2), 256, ATTN_SMEM_BYTES>>>(rel_table, out);
}

// round 7
// speedup vs baseline: 6.8101x; 1.0741x over previous
#include <cuda_runtime.h>

// Problem constants
#define B_    2
#define C_    128
#define T_    4
#define S_    16384      // T*H*W
#define NH_   32
#define N_    1024       // T*h*w = 4*16*16
#define TABSZ 6727       // (2T-1)*(2h-1)*(2w-1) = 7*31*31
#define EPS_  1e-5f

// ---------------- scratch (static device globals; no runtime alloc) -------
__device__ float g_stat[3][B_][32][2];      // groupnorm sum / sumsq partials
__device__ float g_aff[3][B_][C_][2];       // per-channel affine (a, b)
__device__ float g_qp[B_][NH_][N_][4];      // pooled Q: raw sums -> normalized
__device__ float g_kp[B_][NH_][N_][4];      // pooled K: raw sums -> normalized
__device__ float g_vp[B_][NH_][N_][64];     // RAW V, tf32-rounded, vp layout

// ---------------- tf32 / mma helpers ---------------------------------------
__device__ __forceinline__ unsigned tf32r(float f) {
    unsigned u; asm("cvt.rna.tf32.f32 %0, %1;" : "=r"(u) : "f"(f)); return u;
}
__device__ __forceinline__ void mma_tf32(float* d, unsigned a0, unsigned a1,
                                         unsigned a2, unsigned a3,
                                         unsigned b0, unsigned b1) {
    asm("mma.sync.aligned.m16n8k8.row.col.f32.tf32.tf32.f32 "
        "{%0,%1,%2,%3}, {%4,%5,%6,%7}, {%8,%9}, {%0,%1,%2,%3};"
        : "+f"(d[0]), "+f"(d[1]), "+f"(d[2]), "+f"(d[3])
        : "r"(a0), "r"(a1), "r"(a2), "r"(a3), "r"(b0), "r"(b1));
}
// split fp32 into tf32-hi (masked bits) + exact fp32 residual
__device__ __forceinline__ void split32(float f, unsigned& hi, unsigned& lo) {
    unsigned u = __float_as_uint(f);
    hi = u & 0xFFFFE000u;
    lo = __float_as_uint(f - __uint_as_float(hi));
}

// ---------------- cp.async helpers ----------------------------------------
__device__ __forceinline__ void cp16(void* smem, const void* g) {
    unsigned sa = (unsigned)__cvta_generic_to_shared(smem);
    asm volatile("cp.async.cg.shared.global [%0], [%1], 16;" :: "r"(sa), "l"(g));
}
__device__ __forceinline__ void cp_commit() {
    asm volatile("cp.async.commit_group;");
}
__device__ __forceinline__ void cp_wait0() {
    asm volatile("cp.async.wait_group 0;" ::: "memory");
}
__device__ __forceinline__ void cp_wait1() {
    asm volatile("cp.async.wait_group 1;" ::: "memory");
}

// ================= K0: zero accumulators ===================================
__global__ void zero_kernel() {      // <<<512, 256>>>
    int idx = blockIdx.x * 256 + threadIdx.x;       // 0..131071
    float4 z = make_float4(0.f, 0.f, 0.f, 0.f);
    if (idx < 65536) ((float4*)g_qp)[idx] = z;      // 262144 floats
    else             ((float4*)g_kp)[idx - 65536] = z;
    if (idx < 96)    ((float4*)g_stat)[idx] = z;    // 384 floats
}

// ================= K1: projections via 3xTF32 tensor-core GEMM =============
// Per CTA: 128 o x 64 s tile; K=128 in 4 chunks of 32c, double-buffered
// cp.async. Warp = (ow 0..3, sw 0..1): 32 o (2 m16) x 32 s (4 n8).
// Epilogues (no z intermediate!):
//   pr 0/1 (q,k): in-warp patch-sum -> atomicAdd raw pooled sums to g_qp/g_kp
//   pr 2   (v)  : stage D tile in smem, scatter tf32(raw) into vp layout
// GroupNorm partial stats fused for all three.
#define WS_PITCH 36
#define XS_PITCH 72
#define WS_STAGE (128 * WS_PITCH)     // 4608 floats
#define XS_STAGE (32 * XS_PITCH)      // 2304 floats
#define SB_OFF   (2 * WS_STAGE + 2 * XS_STAGE)
#define PROJ_SMEM_FLOATS (SB_OFF + 512)
#define PROJ_SMEM_BYTES  (PROJ_SMEM_FLOATS * 4)

__global__ __launch_bounds__(256, 2) void proj_kernel(
    const float* __restrict__ x, const float* __restrict__ Wq,
    const float* __restrict__ Wk, const float* __restrict__ Wv) {
    extern __shared__ float sm[];
    float* Ws   = sm;                         // [stage][o:128][c:32] pitch 36
    float* Xs   = sm + 2 * WS_STAGE;          // [stage][c:32][s:64] pitch 72
    float* sbuf = sm + SB_OFF;                // 512: stats partials

    const int pr = blockIdx.z;
    const float* Wsel = (pr == 0) ? Wq : ((pr == 1) ? Wk : Wv);
    const int b   = blockIdx.y;
    const int s_t = blockIdx.x << 6;
    const int tid = threadIdx.x;
    const float* xb = x + (size_t)b * C_ * S_;

    auto issue = [&](int kc, int st) {
        float* wd = Ws + st * WS_STAGE;
        float* xd = Xs + st * XS_STAGE;
#pragma unroll
        for (int j = 0; j < 4; j++) {
            int e = tid + 256 * j;
            int o = e >> 3, seg = e & 7;
            cp16(wd + o * WS_PITCH + seg * 4, Wsel + o * 128 + kc * 32 + seg * 4);
        }
#pragma unroll
        for (int j = 0; j < 2; j++) {
            int e = tid + 256 * j;
            int c = e >> 4, seg = e & 15;
            cp16(xd + c * XS_PITCH + seg * 4,
                 xb + (size_t)(kc * 32 + c) * S_ + s_t + seg * 4);
        }
        cp_commit();
    };

    const int warp = tid >> 5, lane = tid & 31;
    const int gid = lane >> 2, tg = lane & 3;
    const int ow = warp >> 1, sw = warp & 1;
    const int o0 = ow << 5;
    const int sbase = sw << 5;

    float acc[2][4][4];
#pragma unroll
    for (int mb = 0; mb < 2; mb++)
#pragma unroll
        for (int nb = 0; nb < 4; nb++)
#pragma unroll
            for (int i = 0; i < 4; i++) acc[mb][nb][i] = 0.f;

    issue(0, 0);
    for (int kc = 0; kc < 4; kc++) {
        cp_wait0();
        __syncthreads();
        if (kc < 3) issue(kc + 1, (kc + 1) & 1);
        const float* Wb = Ws + (kc & 1) * WS_STAGE;
        const float* Xb = Xs + (kc & 1) * XS_STAGE;

#pragma unroll
        for (int ks = 0; ks < 4; ks++) {
            unsigned bh[4][2], bl[4][2];
#pragma unroll
            for (int nb = 0; nb < 4; nb++) {
                const float* xp = Xb + (ks * 8 + tg) * XS_PITCH
                                + sbase + nb * 8 + gid;
                split32(xp[0],            bh[nb][0], bl[nb][0]);
                split32(xp[4 * XS_PITCH], bh[nb][1], bl[nb][1]);
            }
#pragma unroll
            for (int mb = 0; mb < 2; mb++) {
                const float* wp0 = Wb + (o0 + mb * 16 + gid) * WS_PITCH
                                 + ks * 8 + tg;
                const float* wp1 = wp0 + 8 * WS_PITCH;
                unsigned ah0, ah1, ah2, ah3, al0, al1, al2, al3;
                split32(wp0[0], ah0, al0);
                split32(wp1[0], ah1, al1);
                split32(wp0[4], ah2, al2);
                split32(wp1[4], ah3, al3);
#pragma unroll
                for (int nb = 0; nb < 4; nb++) {
                    mma_tf32(acc[mb][nb], ah0, ah1, ah2, ah3, bh[nb][0], bh[nb][1]);
                    mma_tf32(acc[mb][nb], ah0, ah1, ah2, ah3, bl[nb][0], bl[nb][1]);
                    mma_tf32(acc[mb][nb], al0, al1, al2, al3, bh[nb][0], bh[nb][1]);
                }
            }
        }
        __syncthreads();
    }

    // ---- epilogue coordinates
    const int t  = s_t >> 12;
    const int hh = (s_t >> 6) & 63;
    const int y  = hh >> 2, sy = hh & 3;
    const int nbase = t * 256 + (y << 4);

    if (pr < 2) {
        // ---- pooled q/k: patch partial sums -> atomicAdd raw sums
        float* dstp = (pr == 0) ? &g_qp[0][0][0][0] : &g_kp[0][0][0][0];
#pragma unroll
        for (int mb = 0; mb < 2; mb++) {
            const int cA = o0 + mb * 16 + gid, cB = cA + 8;
#pragma unroll
            for (int nb = 0; nb < 4; nb++) {
                float sA = acc[mb][nb][0] + acc[mb][nb][1];
                float sB = acc[mb][nb][2] + acc[mb][nb][3];
                sA += __shfl_xor_sync(0xffffffffu, sA, 1);
                sB += __shfl_xor_sync(0xffffffffu, sB, 1);
                if ((tg & 1) == 0) {
                    int n = nbase + (sw << 3) + (nb << 1) + (tg >> 1);
                    atomicAdd(dstp + (((size_t)(b * 32 + (cA >> 2)) * 1024 + n) << 2)
                                   + (cA & 3), sA);
                    atomicAdd(dstp + (((size_t)(b * 32 + (cB >> 2)) * 1024 + n) << 2)
                                   + (cB & 3), sB);
                }
            }
        }
    } else {
        // ---- stage v tile [c][s] in smem (overlaps Ws; safe after last sync)
        float* Zs = sm;                      // 128 rows x pitch 72 = 9216 < 2*WS_STAGE
#pragma unroll
        for (int mb = 0; mb < 2; mb++) {
            const int r = o0 + mb * 16 + gid;
#pragma unroll
            for (int nb = 0; nb < 4; nb++) {
                int col = sbase + nb * 8 + (tg << 1);
                *(float2*)&Zs[r * 72 + col]       = make_float2(acc[mb][nb][0], acc[mb][nb][1]);
                *(float2*)&Zs[(r + 8) * 72 + col] = make_float2(acc[mb][nb][2], acc[mb][nb][3]);
            }
        }
    }

    // ---- fused GroupNorm partial stats (common; sbuf disjoint from Zs)
#pragma unroll
    for (int mb = 0; mb < 2; mb++)
#pragma unroll
        for (int hi = 0; hi < 2; hi++) {
            float s = 0.f, s2 = 0.f;
#pragma unroll
            for (int nb = 0; nb < 4; nb++) {
                float v0 = acc[mb][nb][hi * 2 + 0];
                float v1 = acc[mb][nb][hi * 2 + 1];
                s += v0 + v1;
                s2 = fmaf(v0, v0, s2); s2 = fmaf(v1, v1, s2);
            }
            s  += __shfl_xor_sync(0xffffffffu, s, 1);
            s  += __shfl_xor_sync(0xffffffffu, s, 2);
            s2 += __shfl_xor_sync(0xffffffffu, s2, 1);
            s2 += __shfl_xor_sync(0xffffffffu, s2, 2);
            if (tg == 0) {
                int idx = (((warp << 3) | gid) << 3) | (mb << 2) | (hi << 1);
                sbuf[idx]     = s;
                sbuf[idx + 1] = s2;
            }
        }
    __syncthreads();

    if (pr == 2) {
        // ---- scatter raw tf32 v into vp layout
        const float* Zs = sm;
#pragma unroll
        for (int j = 0; j < 8; j++) {
            int e = tid + (j << 8);              // 2048 float4
            int c = e >> 4, xq = e & 15;
            float4 v = *(const float4*)&Zs[c * 72 + (xq << 2)];
            float4 r = make_float4(
                __uint_as_float(tf32r(v.x)), __uint_as_float(tf32r(v.y)),
                __uint_as_float(tf32r(v.z)), __uint_as_float(tf32r(v.w)));
            *(float4*)&g_vp[b][c >> 2][nbase + xq][((c & 3) << 4) + (sy << 2)] = r;
        }
    }
    if (tid < 64) {
        int grp = tid >> 1, v = tid & 1;
        float tot = 0.f;
#pragma unroll
        for (int ci = 0; ci < 4; ci++) {
            int ch = (grp << 2) + ci;
            int cow = ch >> 5, r = ch & 31;
            int cmb = r >> 4, chi = (r >> 3) & 1, cgid = r & 7;
#pragma unroll
            for (int csw = 0; csw < 2; csw++) {
                int w2 = (cow << 1) | csw;
                tot += sbuf[(((w2 << 3) | cgid) << 3) | (cmb << 2) | (chi << 1) | v];
            }
        }
        atomicAdd(&g_stat[pr][b][grp][v], tot);
    }
}

// ================= K2: finalize stats -> per-channel affine ================
__global__ void finalize_stats(
    const float* __restrict__ gqg, const float* __restrict__ gqb,
    const float* __restrict__ gkg, const float* __restrict__ gkb,
    const float* __restrict__ gvg, const float* __restrict__ gvb) {   // <<<1,192>>>
    int i = threadIdx.x;
    int pr = i >> 6, r = i & 63, b = r >> 5, grp = r & 31;
    float s  = g_stat[pr][b][grp][0];
    float s2 = g_stat[pr][b][grp][1];
    float mean = s * (1.f / 65536.f);
    float var  = s2 * (1.f / 65536.f) - mean * mean;
    float rstd = rsqrtf(var + EPS_);
    const float* ga = (pr == 0) ? gqg : ((pr == 1) ? gkg : gvg);
    const float* be = (pr == 0) ? gqb : ((pr == 1) ? gkb : gvb);
#pragma unroll
    for (int d = 0; d < 4; d++) {
        int c = (grp << 2) + d;
        float a = rstd * ga[c];
        g_aff[pr][b][c][0] = a;
        g_aff[pr][b][c][1] = be[c] - mean * a;
    }
}

// ================= K3: normalize pooled q/k in place =======================
__global__ __launch_bounds__(256) void qknorm_kernel() {   // <<<1024, 256>>>
    int flat = blockIdx.x * 256 + threadIdx.x;   // 262144 = [b][g][n][dd]
    int dd = flat & 3, g = (flat >> 12) & 31, b = flat >> 17;
    int c = (g << 2) + dd;
    float aq = g_aff[0][b][c][0], bq = g_aff[0][b][c][1];
    float ak = g_aff[1][b][c][0], bk = g_aff[1][b][c][1];
    float* q = &g_qp[0][0][0][0] + flat;
    float* k = &g_kp[0][0][0][0] + flat;
    *q = fmaf(*q * 0.0625f, aq, bq);
    *k = fmaf(*k * 0.0625f, ak, bk);
}

// ================= K4: fused tensor-core patch attention ===================
// CTA = (b, head, 128 rows). V is RAW (tf32); the GroupNorm affine for V is
// applied per-column in the epilogue: out = a_c * (acc/wsum) + b_c.
#define VSP_    72
#define VS_BUF  (64 * VSP_)                 // 4608 floats per stage
#define SM_TAB  0
#define SM_K    6728                        // 1024 float4
#define SM_KC   (SM_K + 4096)               // 1024 ints
#define SM_VS   (SM_KC + 1024)              // 3 * 4608
#define SM_RED  (SM_VS + 3 * VS_BUF)        // 16
#define ATTN_SMEM_FLOATS (SM_RED + 16)
#define ATTN_SMEM_BYTES (ATTN_SMEM_FLOATS * 4)

__global__ __launch_bounds__(256, 2) void attn_kernel(
    const float* __restrict__ rel_table, float* __restrict__ out) {
    extern __shared__ float sm[];
    float*  tab  = sm + SM_TAB;
    float4* ks4  = (float4*)(sm + SM_K);
    int*    kc   = (int*)(sm + SM_KC);
    float*  vsb0 = sm + SM_VS;
    float*  red  = sm + SM_RED;

    const int b = blockIdx.z, g = blockIdx.y;
    const int n0 = blockIdx.x << 7;
    const int tid = threadIdx.x;

    // ---- kick off V chunks 0 and 1 immediately
#pragma unroll
    for (int st = 0; st < 2; st++) {
        const float4* vsrc = (const float4*)&g_vp[b][g][st << 6][0];
        float* vdst = vsb0 + st * VS_BUF;
#pragma unroll
        for (int j = 0; j < 4; j++) {
            int idx = tid + 256 * j;
            int row = idx >> 4, seg = idx & 15;
            cp16(vdst + row * VSP_ + seg * 4, (const float*)vsrc + row * 64 + seg * 4);
        }
        cp_commit();
    }

    // ---- load bias table, K, kc; reduce tmax / knmax
    float tmax = -1e30f;
    for (int i = tid; i < TABSZ; i += 256) {
        float v = rel_table[g * TABSZ + i];
        tab[i] = v;
        tmax = fmaxf(tmax, v);
    }
    float knmax = 0.f;
    for (int i = tid; i < 1024; i += 256) {
        float4 kk = *(const float4*)&g_kp[b][g][i][0];
        ks4[i] = kk;
        kc[i]  = 961 * (i >> 8) + 31 * ((i >> 4) & 15) + (i & 15);
        float nn = fmaf(kk.x, kk.x, fmaf(kk.y, kk.y, fmaf(kk.z, kk.z, kk.w * kk.w)));
        knmax = fmaxf(knmax, nn);
    }
#pragma unroll
    for (int o = 16; o; o >>= 1) {
        tmax  = fmaxf(tmax,  __shfl_xor_sync(0xffffffffu, tmax,  o));
        knmax = fmaxf(knmax, __shfl_xor_sync(0xffffffffu, knmax, o));
    }
    int w = tid >> 5;
    if ((tid & 31) == 0) { red[w] = tmax; red[8 + w] = knmax; }
    __syncthreads();
    tmax = red[0]; knmax = red[8];
#pragma unroll
    for (int i = 1; i < 8; i++) {
        tmax = fmaxf(tmax, red[i]); knmax = fmaxf(knmax, red[8 + i]);
    }
    const float kn = sqrtf(knmax);

    // ---- per-thread identity (mma fragment coordinates)
    const int warp = tid >> 5, lane = tid & 31;
    const int gid = lane >> 2, tg = lane & 3;
    const int r0 = (warp << 4) + gid;
    const int nq0 = n0 + r0, nq1 = nq0 + 8;
    const float4 q0 = *(const float4*)&g_qp[b][g][nq0][0];
    const float4 q1 = *(const float4*)&g_qp[b][g][nq1][0];
    const float qq0 = fmaf(q0.x, q0.x, fmaf(q0.y, q0.y, fmaf(q0.z, q0.z, q0.w * q0.w)));
    const float qq1 = fmaf(q1.x, q1.x, fmaf(q1.y, q1.y, fmaf(q1.z, q1.z, q1.w * q1.w)));
    const float bnd0 = fmaf(0.5f * sqrtf(qq0), kn, tmax);
    const float bnd1 = fmaf(0.5f * sqrtf(qq1), kn, tmax);
    const int cn0 = 961 * (nq0 >> 8) + 31 * ((nq0 >> 4) & 15) + (nq0 & 15) + 3363;
    const int cn1 = 961 * (nq1 >> 8) + 31 * ((nq1 >> 4) & 15) + (nq1 & 15) + 3363;

    float acc[8][4];
#pragma unroll
    for (int j = 0; j < 8; j++)
#pragma unroll
        for (int i = 0; i < 4; i++) acc[j][i] = 0.f;
    float wsum0 = 0.f, wsum1 = 0.f;

    // ---- main loop: 16 chunks of 64 keys, 3-stage cp.async ring
    for (int mc = 0; mc < 16; mc++) {
        if (mc < 15) cp_wait1(); else cp_wait0();
        __syncthreads();
        if (mc + 2 < 16) {
            const float4* vsrc = (const float4*)&g_vp[b][g][(mc + 2) << 6][0];
            float* vdst = vsb0 + ((mc + 2) % 3) * VS_BUF;
#pragma unroll
            for (int j = 0; j < 4; j++) {
                int idx = tid + 256 * j;
                int row = idx >> 4, seg = idx & 15;
                cp16(vdst + row * VSP_ + seg * 4,
                     (const float*)vsrc + row * 64 + seg * 4);
            }
            cp_commit();
        }
        const float* vsb = vsb0 + (mc % 3) * VS_BUF;
        const int m0 = mc << 6;

#pragma unroll
        for (int sub = 0; sub < 8; sub++) {
            const int mk = m0 + (sub << 3);
            float4 k0 = ks4[mk + tg];
            float4 k1 = ks4[mk + tg + 4];
            int c0i = kc[mk + tg], c1i = kc[mk + tg + 4];

            float d00 = fmaf(q0.x, k0.x, fmaf(q0.y, k0.y, fmaf(q0.z, k0.z, q0.w * k0.w)));
            float d01 = fmaf(q0.x, k1.x, fmaf(q0.y, k1.y, fmaf(q0.z, k1.z, q0.w * k1.w)));
            float d10 = fmaf(q1.x, k0.x, fmaf(q1.y, k0.y, fmaf(q1.z, k0.z, q1.w * k0.w)));
            float d11 = fmaf(q1.x, k1.x, fmaf(q1.y, k1.y, fmaf(q1.z, k1.z, q1.w * k1.w)));

            float w00 = __expf(fmaf(d00, 0.5f, tab[cn0 - c0i]) - bnd0);
            float w01 = __expf(fmaf(d01, 0.5f, tab[cn0 - c1i]) - bnd0);
            float w10 = __expf(fmaf(d10, 0.5f, tab[cn1 - c0i]) - bnd1);
            float w11 = __expf(fmaf(d11, 0.5f, tab[cn1 - c1i]) - bnd1);
            wsum0 += w00 + w01;
            wsum1 += w10 + w11;

            unsigned a0 = __float_as_uint(w00), a1 = __float_as_uint(w10);
            unsigned a2 = __float_as_uint(w01), a3 = __float_as_uint(w11);

            const float* vr0 = vsb + ((sub << 3) + tg) * VSP_ + gid;
            const float* vr1 = vr0 + 4 * VSP_;
#pragma unroll
            for (int j = 0; j < 8; j++) {
                unsigned b0 = __float_as_uint(vr0[8 * j]);
                unsigned b1 = __float_as_uint(vr1[8 * j]);
                mma_tf32(acc[j], a0, a1, a2, a3, b0, b1);
            }
        }
    }

    // ---- exact row sums (fp32), deferred V affine, epilogue
    wsum0 += __shfl_xor_sync(0xffffffffu, wsum0, 1);
    wsum0 += __shfl_xor_sync(0xffffffffu, wsum0, 2);
    wsum1 += __shfl_xor_sync(0xffffffffu, wsum1, 1);
    wsum1 += __shfl_xor_sync(0xffffffffu, wsum1, 2);
    const float inv0 = 1.f / wsum0, inv1 = 1.f / wsum1;

    float avA[4], avB[4];
#pragma unroll
    for (int dd = 0; dd < 4; dd++) {
        avA[dd] = g_aff[2][b][(g << 2) + dd][0];
        avB[dd] = g_aff[2][b][(g << 2) + dd][1];
    }

    const int t0 = nq0 >> 8, y0 = (nq0 >> 4) & 15, x0 = nq0 & 15;
    const int t1 = nq1 >> 8, y1 = (nq1 >> 4) & 15, x1 = nq1 & 15;
    const size_t ob0 = ((size_t)(b * C_) + (g << 2)) * S_
                     + t0 * 4096 + (y0 << 2) * 64 + (x0 << 2);
    const size_t ob1 = ((size_t)(b * C_) + (g << 2)) * S_
                     + t1 * 4096 + (y1 << 2) * 64 + (x1 << 2);
#pragma unroll
    for (int j = 0; j < 8; j++) {
        int col = 8 * j + 2 * tg;
        int dd = col >> 4, p = col & 15;
        int sy = p >> 2, sx = p & 3;
        size_t off = (size_t)dd * S_ + sy * 64 + sx;
        *(float2*)&out[ob0 + off] = make_float2(
            fmaf(acc[j][0] * inv0, avA[dd], avB[dd]),
            fmaf(acc[j][1] * inv0, avA[dd], avB[dd]));
        *(float2*)&out[ob1 + off] = make_float2(
            fmaf(acc[j][2] * inv1, avA[dd], avB[dd]),
            fmaf(acc[j][3] * inv1, avA[dd], avB[dd]));
    }
}

// ================= launch ==================================================
extern "C" void kernel_launch(void* const* d_in, const int* in_sizes, int n_in,
                              void* d_out, int out_size) {
    const float* x   = (const float*)d_in[0];
    const float* Wq  = (const float*)d_in[1];
    const float* Wk  = (const float*)d_in[2];
    const float* Wv  = (const float*)d_in[3];
    const float* gqg = (const float*)d_in[4];
    const float* gqb = (const float*)d_in[5];
    const float* gkg = (const float*)d_in[6];
    const float* gkb = (const float*)d_in[7];
    const float* gvg = (const float*)d_in[8];
    const float* gvb = (const float*)d_in[9];
    const float* rel_table = (const float*)d_in[10];
    // d_in[11] = rel_index: unused (computed analytically in-kernel)
    float* out = (float*)d_out;

    cudaFuncSetAttribute(proj_kernel, cudaFuncAttributeMaxDynamicSharedMemorySize,
                         PROJ_SMEM_BYTES);
    cudaFuncSetAttribute(attn_kernel, cudaFuncAttributeMaxDynamicSharedMemorySize,
                         ATTN_SMEM_BYTES);

    zero_kernel<<<512, 256>>>();
    proj_kernel<<<dim3(256, 2, 3), 256, PROJ_SMEM_BYTES>>>(x, Wq, Wk, Wv);
    finalize_stats<<<1, 192>>>(gqg, gqb, gkg, gkb, gvg, gvb);
    qknorm_kernel<<<1024, 256>>>();
    attn_kernel<<<dim3(8, 32, 2), 256, ATTN_SMEM_BYTES>>>(rel_table, out);
}